// round 6
// baseline (speedup 1.0000x reference)
#include <cuda_runtime.h>
#include <cuda_fp16.h>
#include <math.h>

#define B_   64
#define N_   197
#define C_   768
#define H_   12
#define DH_  64
#define R_   98
#define K_   99
#define NKEPT_ 98
#define THRK_ 1941
#define ALPHA_ 0.1f
#define EPS_ 1e-5f

// ---------------- scratch ----------------
__device__ float    g_qkv [(size_t)B_*N_*3*C_];
__device__ float    g_attn[(size_t)B_*H_*N_*N_];
__device__ float    g_x1  [(size_t)B_*N_*C_];
__device__ float    g_x2  [(size_t)B_*K_*C_];
__device__ int      g_ik  [B_*K_];
__device__ int      g_ie  [B_*R_];
// packed fp16 operands (half2 along K)
__device__ unsigned g_hh  [(size_t)B_*N_*C_/2];      // LN1 out hi
__device__ unsigned g_hl  [(size_t)B_*N_*C_/2];      // LN1 out lo
__device__ unsigned g_wqkvh[(size_t)C_/2*3*C_];
__device__ unsigned g_wqkvl[(size_t)C_/2*3*C_];
__device__ unsigned g_wprojh[(size_t)C_/2*C_];
__device__ unsigned g_wfc1h[(size_t)C_/2*4*C_];
__device__ unsigned g_wfc2h[(size_t)4*C_/2*C_];
__device__ unsigned g_aoh [(size_t)B_*N_*C_/2];      // attention out
__device__ unsigned g_h2h [(size_t)B_*K_*C_/2];      // LN2 out
__device__ unsigned g_mlph[(size_t)B_*K_*4*C_/2];    // fc1 out

// ---------------- helpers ----------------
__device__ __forceinline__ unsigned packh2(float a, float b) {
    __half2 h = __floats2half2_rn(a, b);
    return *reinterpret_cast<unsigned*>(&h);
}
__device__ __forceinline__ void splith2(float a, float b, unsigned& hi, unsigned& lo) {
    __half ah = __float2half_rn(a), bh = __float2half_rn(b);
    __half2 h = __halves2half2(ah, bh);
    hi = *reinterpret_cast<unsigned*>(&h);
    lo = packh2(a - __half2float(ah), b - __half2float(bh));
}
__device__ __forceinline__ void mma_f16(float c[4], const unsigned a[4], const unsigned b[2]) {
    asm volatile(
        "mma.sync.aligned.m16n8k16.row.col.f32.f16.f16.f32 "
        "{%0,%1,%2,%3},{%4,%5,%6,%7},{%8,%9},{%0,%1,%2,%3};"
        : "+f"(c[0]), "+f"(c[1]), "+f"(c[2]), "+f"(c[3])
        : "r"(a[0]), "r"(a[1]), "r"(a[2]), "r"(a[3]), "r"(b[0]), "r"(b[1]));
}

// ---------------- weight pack: [K][N] fp32 -> [K/2][N] half2 (hi, opt lo) ----------------
template<int SPLIT>
__global__ void cvtw_pack(const float* __restrict__ w, unsigned* __restrict__ hi,
                          unsigned* __restrict__ lo, int Nd, int totalWords)
{
    int idx = blockIdx.x * 256 + threadIdx.x;
    if (idx >= totalWords) return;
    int kk = idx / Nd, n = idx - kk * Nd;
    float e = w[(size_t)(2 * kk) * Nd + n];
    float o = w[(size_t)(2 * kk + 1) * Nd + n];
    if (SPLIT) {
        unsigned h, l;
        splith2(e, o, h, l);
        hi[idx] = h; lo[idx] = l;
    } else {
        hi[idx] = packh2(e, o);
    }
}

// ---------------- LayerNorm -> packed fp16 hi(/lo) ----------------
template<int SPLIT>
__global__ void ln_pack_kernel(const float* __restrict__ x, const float* __restrict__ g,
                               const float* __restrict__ bta,
                               unsigned* __restrict__ hi, unsigned* __restrict__ lo)
{
    int row = blockIdx.x;
    const float2* xr = (const float2*)(x + (size_t)row * C_);
    int tid = threadIdx.x;
    float2 v1 = xr[tid];
    float2 v2 = make_float2(0.f, 0.f);
    if (tid < 128) v2 = xr[tid + 256];
    float s = v1.x + v1.y + v2.x + v2.y;
    float ss = v1.x * v1.x + v1.y * v1.y + v2.x * v2.x + v2.y * v2.y;
    for (int off = 16; off; off >>= 1) {
        s  += __shfl_xor_sync(0xffffffffu, s, off);
        ss += __shfl_xor_sync(0xffffffffu, ss, off);
    }
    __shared__ float rs[8], rss[8];
    __shared__ float smean, srstd;
    int w = tid >> 5;
    if ((tid & 31) == 0) { rs[w] = s; rss[w] = ss; }
    __syncthreads();
    if (tid == 0) {
        float S = 0.f, SS = 0.f;
        for (int i = 0; i < 8; i++) { S += rs[i]; SS += rss[i]; }
        float mean = S * (1.f / C_);
        float var = SS * (1.f / C_) - mean * mean;
        smean = mean; srstd = rsqrtf(var + EPS_);
    }
    __syncthreads();
    float mean = smean, rstd = srstd;
    size_t base = (size_t)row * (C_ / 2);
#pragma unroll
    for (int p = 0; p < 2; p++) {
        if (p == 1 && tid >= 128) break;
        int wi = tid + p * 256;
        float2 v = (p == 0) ? v1 : v2;
        int c = wi * 2;
        float a = (v.x - mean) * rstd * g[c] + bta[c];
        float b = (v.y - mean) * rstd * g[c + 1] + bta[c + 1];
        if (SPLIT) {
            unsigned h, l;
            splith2(a, b, h, l);
            hi[base + wi] = h; lo[base + wi] = l;
        } else {
            hi[base + wi] = packh2(a, b);
        }
    }
}

// ---------------- fp16 tensor GEMM: 64x128 tiles, k-step 32, m16n8k16 ----------------
// A packed [M][Kd/2], B packed [Kd/2][Nd]. SPLIT=1: hi/lo (3 mma). Out: float (ldc) or packed.
#define HA_W 20
#define HASZ (64 * HA_W)
#define HBSZ (16 * 132)
template<int SPLIT, bool GELU, bool HASBIAS, bool HASRES, bool OUTPACK>
__global__ void hgemm_kernel(const unsigned* __restrict__ Ah, const unsigned* __restrict__ Al,
                             const unsigned* __restrict__ Bh, const unsigned* __restrict__ Bl,
                             const float* __restrict__ bias, const float* __restrict__ res,
                             float* __restrict__ Cf, unsigned* __restrict__ Cu,
                             int Nd, int Kd, int ldc)
{
    extern __shared__ unsigned smu[];
    unsigned* AsH = smu;
    unsigned* AsL = AsH + HASZ;
    unsigned* BsH = AsH + HASZ * (1 + SPLIT);
    unsigned* BsL = BsH + HBSZ;

    int tid = threadIdx.x;
    int lane = tid & 31, wid = tid >> 5;
    int wm = wid & 1, wn = wid >> 1;
    int g = lane >> 2, tg = lane & 3;
    int m0 = blockIdx.y * 64, n0 = blockIdx.x * 128;
    int Kw = Kd / 2;

    float acc[2][4][4];
#pragma unroll
    for (int i = 0; i < 2; i++)
#pragma unroll
        for (int j = 0; j < 4; j++)
#pragma unroll
            for (int q = 0; q < 4; q++) acc[i][j][q] = 0.f;

    int am = tid >> 2;            // 0..63
    int aw = (tid & 3) * 4;       // word col
    int bkw = tid >> 5;           // 0..7 (and +8)
    int bn4 = (tid & 31) * 4;

    for (int k0w = 0; k0w < Kw; k0w += 16) {
        uint4 avh = *(const uint4*)&Ah[(size_t)(m0 + am) * Kw + k0w + aw];
        uint4 avl;
        if (SPLIT) avl = *(const uint4*)&Al[(size_t)(m0 + am) * Kw + k0w + aw];
        uint4 bvh0 = *(const uint4*)&Bh[(size_t)(k0w + bkw) * Nd + n0 + bn4];
        uint4 bvh1 = *(const uint4*)&Bh[(size_t)(k0w + bkw + 8) * Nd + n0 + bn4];
        uint4 bvl0, bvl1;
        if (SPLIT) {
            bvl0 = *(const uint4*)&Bl[(size_t)(k0w + bkw) * Nd + n0 + bn4];
            bvl1 = *(const uint4*)&Bl[(size_t)(k0w + bkw + 8) * Nd + n0 + bn4];
        }
        __syncthreads();
        *(uint4*)&AsH[am * HA_W + aw] = avh;
        if (SPLIT) *(uint4*)&AsL[am * HA_W + aw] = avl;
        *(uint4*)&BsH[bkw * 132 + bn4] = bvh0;
        *(uint4*)&BsH[(bkw + 8) * 132 + bn4] = bvh1;
        if (SPLIT) {
            *(uint4*)&BsL[bkw * 132 + bn4] = bvl0;
            *(uint4*)&BsL[(bkw + 8) * 132 + bn4] = bvl1;
        }
        __syncthreads();

        int arow = wm * 32 + g;
#pragma unroll
        for (int s = 0; s < 2; s++) {
            unsigned ah[2][4], al[2][4];
#pragma unroll
            for (int mf = 0; mf < 2; mf++) {
                int base = (arow + mf * 16) * HA_W + s * 8 + tg;
                ah[mf][0] = AsH[base];
                ah[mf][1] = AsH[base + 8 * HA_W];
                ah[mf][2] = AsH[base + 4];
                ah[mf][3] = AsH[base + 8 * HA_W + 4];
                if (SPLIT) {
                    al[mf][0] = AsL[base];
                    al[mf][1] = AsL[base + 8 * HA_W];
                    al[mf][2] = AsL[base + 4];
                    al[mf][3] = AsL[base + 8 * HA_W + 4];
                }
            }
            unsigned bh[4][2], bl[4][2];
#pragma unroll
            for (int nf = 0; nf < 4; nf++) {
                int n = wn * 32 + nf * 8 + g;
                bh[nf][0] = BsH[(s * 8 + tg) * 132 + n];
                bh[nf][1] = BsH[(s * 8 + tg + 4) * 132 + n];
                if (SPLIT) {
                    bl[nf][0] = BsL[(s * 8 + tg) * 132 + n];
                    bl[nf][1] = BsL[(s * 8 + tg + 4) * 132 + n];
                }
            }
#pragma unroll
            for (int mf = 0; mf < 2; mf++)
#pragma unroll
                for (int nf = 0; nf < 4; nf++) {
                    mma_f16(acc[mf][nf], ah[mf], bh[nf]);
                    if (SPLIT) {
                        mma_f16(acc[mf][nf], ah[mf], bl[nf]);
                        mma_f16(acc[mf][nf], al[mf], bh[nf]);
                    }
                }
        }
    }

    // epilogue
#pragma unroll
    for (int mf = 0; mf < 2; mf++) {
        int row = m0 + wm * 32 + mf * 16 + g;
#pragma unroll
        for (int nf = 0; nf < 4; nf++) {
            int col = n0 + wn * 32 + nf * 8 + 2 * tg;
            float b0 = 0.f, b1 = 0.f;
            if (HASBIAS) { b0 = bias[col]; b1 = bias[col + 1]; }
#pragma unroll
            for (int half = 0; half < 2; half++) {
                int r = row + half * 8;
                float c0 = acc[mf][nf][half * 2 + 0] + b0;
                float c1 = acc[mf][nf][half * 2 + 1] + b1;
                if (GELU) {
                    c0 = 0.5f * c0 * (1.f + erff(c0 * 0.70710678118654752f));
                    c1 = 0.5f * c1 * (1.f + erff(c1 * 0.70710678118654752f));
                }
                if (OUTPACK) {
                    Cu[(size_t)r * (Nd / 2) + col / 2] = packh2(c0, c1);
                } else {
                    size_t base = (size_t)r * ldc + col;
                    if (HASRES) {
                        float2 rv = *(const float2*)&res[base];
                        c0 += rv.x; c1 += rv.y;
                    }
                    float2 ov; ov.x = c0; ov.y = c1;
                    *(float2*)&Cf[base] = ov;
                }
            }
        }
    }
}

// ---------------- scores: S = (Q*scale) @ K^T (fp32, rank-critical) ----------------
__global__ void score_kernel(const float* __restrict__ qkv, float* __restrict__ attn)
{
    __shared__ float Qs[64][68];
    __shared__ float Ks[64][68];
    int bh = blockIdx.x;
    int b = bh / H_, hh = bh % H_;
    int m0 = blockIdx.y * 64, n0 = blockIdx.z * 64;
    int tid = threadIdx.x;

#pragma unroll
    for (int r = 0; r < 4; r++) {
        int i = tid + r * 256;
        int row = i >> 4, col4 = (i & 15) * 4;
        int mq = m0 + row, nk = n0 + row;
        float4 q = make_float4(0.f, 0.f, 0.f, 0.f);
        float4 k = make_float4(0.f, 0.f, 0.f, 0.f);
        if (mq < N_) q = *(const float4*)&qkv[(size_t)(b * N_ + mq) * 2304 + hh * 64 + col4];
        if (nk < N_) k = *(const float4*)&qkv[(size_t)(b * N_ + nk) * 2304 + 768 + hh * 64 + col4];
        Qs[col4 + 0][row] = q.x * 0.125f;
        Qs[col4 + 1][row] = q.y * 0.125f;
        Qs[col4 + 2][row] = q.z * 0.125f;
        Qs[col4 + 3][row] = q.w * 0.125f;
        Ks[col4 + 0][row] = k.x;
        Ks[col4 + 1][row] = k.y;
        Ks[col4 + 2][row] = k.z;
        Ks[col4 + 3][row] = k.w;
    }
    __syncthreads();

    int my = tid >> 4, nx = tid & 15;
    float acc[4][4];
#pragma unroll
    for (int i = 0; i < 4; i++)
#pragma unroll
        for (int j = 0; j < 4; j++) acc[i][j] = 0.f;
#pragma unroll
    for (int d = 0; d < 64; d++) {
        float4 a = *(const float4*)&Qs[d][my * 4];
        float4 bb = *(const float4*)&Ks[d][nx * 4];
        float av[4] = {a.x, a.y, a.z, a.w};
        float bv[4] = {bb.x, bb.y, bb.z, bb.w};
#pragma unroll
        for (int i = 0; i < 4; i++)
#pragma unroll
            for (int j = 0; j < 4; j++)
                acc[i][j] = fmaf(av[i], bv[j], acc[i][j]);
    }
#pragma unroll
    for (int i = 0; i < 4; i++) {
        int m = m0 + my * 4 + i;
        if (m >= N_) continue;
        float* arow = attn + ((size_t)bh * N_ + m) * N_;
#pragma unroll
        for (int j = 0; j < 4; j++) {
            int n = n0 + nx * 4 + j;
            if (n < N_) arow[n] = acc[i][j];
        }
    }
}

// ---------------- softmax ----------------
__global__ void softmax_kernel(float* __restrict__ attn)
{
    int row = blockIdx.x * 8 + (threadIdx.x >> 5);
    if (row >= B_ * H_ * N_) return;
    int lane = threadIdx.x & 31;
    float* arow = attn + (size_t)row * N_;
    float v[7];
    float mx = -1e30f;
#pragma unroll
    for (int c = 0; c < 7; c++) {
        int j = lane + c * 32;
        v[c] = (j < N_) ? arow[j] : -1e30f;
        mx = fmaxf(mx, v[c]);
    }
    for (int off = 16; off; off >>= 1) mx = fmaxf(mx, __shfl_xor_sync(0xffffffffu, mx, off));
    float sum = 0.f;
#pragma unroll
    for (int c = 0; c < 7; c++) { float e = expf(v[c] - mx); v[c] = e; sum += e; }
    for (int off = 16; off; off >>= 1) sum += __shfl_xor_sync(0xffffffffu, sum, off);
    float inv = 1.f / sum;
#pragma unroll
    for (int c = 0; c < 7; c++) {
        int j = lane + c * 32;
        if (j < N_) arow[j] = v[c] * inv;
    }
}

// ---------------- AV: O = attn @ V -> packed fp16 ao ----------------
__global__ void av_kernel(const float* __restrict__ qkv, const float* __restrict__ attn,
                          unsigned* __restrict__ aoh)
{
    __shared__ float As[32][68];
    __shared__ float Vs[32][68];
    int bh = blockIdx.x;
    int b = bh / H_, hh = bh % H_;
    int m0 = blockIdx.y * 64;
    int tid = threadIdx.x;
    int my = tid >> 4, nx = tid & 15;

    float acc[4][4];
#pragma unroll
    for (int i = 0; i < 4; i++)
#pragma unroll
        for (int j = 0; j < 4; j++) acc[i][j] = 0.f;

    for (int k0 = 0; k0 < N_; k0 += 32) {
#pragma unroll
        for (int r = 0; r < 8; r++) {
            int i = tid + r * 256;
            int kk = i & 31, mr = i >> 5;
            int m = m0 + mr, kj = k0 + kk;
            As[kk][mr] = (m < N_ && kj < N_) ? attn[((size_t)bh * N_ + m) * N_ + kj] : 0.f;
        }
#pragma unroll
        for (int r = 0; r < 8; r++) {
            int i = tid + r * 256;
            int d = i & 63, kk = i >> 6;
            int kj = k0 + kk;
            Vs[kk][d] = (kj < N_) ? qkv[(size_t)(b * N_ + kj) * 2304 + 1536 + hh * 64 + d] : 0.f;
        }
        __syncthreads();
#pragma unroll
        for (int kk = 0; kk < 32; kk++) {
            float4 a = *(const float4*)&As[kk][my * 4];
            float4 v = *(const float4*)&Vs[kk][nx * 4];
            float av[4] = {a.x, a.y, a.z, a.w};
            float vv[4] = {v.x, v.y, v.z, v.w};
#pragma unroll
            for (int i = 0; i < 4; i++)
#pragma unroll
                for (int j = 0; j < 4; j++)
                    acc[i][j] = fmaf(av[i], vv[j], acc[i][j]);
        }
        __syncthreads();
    }
#pragma unroll
    for (int i = 0; i < 4; i++) {
        int m = m0 + my * 4 + i;
        if (m >= N_) continue;
        size_t base = (size_t)(b * N_ + m) * 384 + hh * 32 + nx * 2;
        aoh[base]     = packh2(acc[i][0], acc[i][1]);
        aoh[base + 1] = packh2(acc[i][2], acc[i][3]);
    }
}

// ---------------- selection ----------------
__global__ void select_kernel(const float* __restrict__ attn, int* __restrict__ ik,
                              int* __restrict__ ie)
{
    __shared__ float diag[196];
    __shared__ int kept[196];
    int b = blockIdx.x, tid = threadIdx.x;
    if (tid < 196) {
        float s = 0.f;
        for (int hh = 0; hh < H_; hh++)
            s += attn[((size_t)(b * H_ + hh) * N_ + (tid + 1)) * N_ + (tid + 1)];
        diag[tid] = s;
    }
    __syncthreads();
    if (tid < 196) {
        float di = diag[tid];
        int rank = 0;
        for (int j = 0; j < 196; j++) {
            float dj = diag[j];
            rank += (dj > di) || (dj == di && j < tid);
        }
        kept[tid] = (rank < NKEPT_) ? 1 : 0;
    }
    __syncthreads();
    if (tid < 196) {
        int mine = kept[tid];
        int pos = 0;
        for (int j = 0; j < tid; j++) pos += (kept[j] == mine);
        if (mine) ik[b * K_ + 1 + pos] = tid + 1;
        else      ie[b * R_ + pos]     = tid + 1;
    }
    if (tid == 0) ik[b * K_] = 0;
}

// ---------------- propagation ----------------
__global__ void propagate_kernel(const float* __restrict__ attn, const float* __restrict__ x1,
                                 const int* __restrict__ ikg, const int* __restrict__ ieg,
                                 float* __restrict__ x2)
{
    extern __shared__ float sm[];
    float* ws = sm;
    float* xe = sm + K_ * R_;
    __shared__ int ik[K_], ie[R_];
    __shared__ int cnt;
    int bh = blockIdx.x;
    int b = bh / H_, hh = bh % H_;
    int tid = threadIdx.x;
    if (tid < K_) ik[tid] = ikg[b * K_ + tid];
    if (tid < R_) ie[tid] = ieg[b * R_ + tid];
    __syncthreads();
    const float* ablk = attn + (size_t)bh * N_ * N_;
    for (int idx = tid; idx < K_ * R_; idx += 256) {
        int k = idx / R_, e = idx - k * R_;
        ws[idx] = ablk[(size_t)ik[k] * N_ + ie[e]];
    }
    for (int idx = tid; idx < R_ * 64; idx += 256) {
        int e = idx >> 6, d = idx & 63;
        xe[idx] = x1[(size_t)(b * N_ + ie[e]) * 768 + hh * 64 + d];
    }
    __syncthreads();

    unsigned lo = 0u, hi = 0x7f7fffffu;
    while (lo < hi) {
        unsigned mid = lo + ((hi - lo + 1) >> 1);
        if (tid == 0) cnt = 0;
        __syncthreads();
        int local = 0;
        for (int i = tid; i < K_ * R_; i += 256)
            local += (__float_as_uint(ws[i]) >= mid);
        for (int off = 16; off; off >>= 1) local += __shfl_xor_sync(0xffffffffu, local, off);
        if ((tid & 31) == 0) atomicAdd(&cnt, local);
        __syncthreads();
        int c = cnt;
        __syncthreads();
        if (c >= THRK_) lo = mid; else hi = mid - 1;
    }
    float thr = __uint_as_float(lo);

    for (int p = tid; p < K_ * 64; p += 256) {
        int k = p >> 6, d = p & 63;
        const float* wr = ws + k * R_;
        float acc = 0.f;
#pragma unroll 2
        for (int e = 0; e < R_; e++) {
            float wv = wr[e];
            wv = (wv >= thr) ? wv : 0.f;
            acc = fmaf(wv, xe[e * 64 + d], acc);
        }
        x2[(size_t)(b * K_ + k) * 768 + hh * 64 + d] =
            x1[(size_t)(b * N_ + ik[k]) * 768 + hh * 64 + d] + ALPHA_ * acc;
    }
}

// ---------------- host ----------------
extern "C" void kernel_launch(void* const* d_in, const int* in_sizes, int n_in,
                              void* d_out, int out_size)
{
    const float* x     = (const float*)d_in[0];
    const float* n1g   = (const float*)d_in[1];
    const float* n1b   = (const float*)d_in[2];
    const float* qkvw  = (const float*)d_in[3];
    const float* projw = (const float*)d_in[4];
    const float* projb = (const float*)d_in[5];
    const float* n2g   = (const float*)d_in[6];
    const float* n2b   = (const float*)d_in[7];
    const float* fc1w  = (const float*)d_in[8];
    const float* fc1b  = (const float*)d_in[9];
    const float* fc2w  = (const float*)d_in[10];
    const float* fc2b  = (const float*)d_in[11];
    float* out = (float*)d_out;

    float *qkv, *attn, *x1, *x2;
    int *ik, *ie;
    unsigned *hh, *hl, *wqkvh, *wqkvl, *wprojh, *wfc1h, *wfc2h, *aoh, *h2h, *mlph;
    cudaGetSymbolAddress((void**)&qkv,  g_qkv);
    cudaGetSymbolAddress((void**)&attn, g_attn);
    cudaGetSymbolAddress((void**)&x1,   g_x1);
    cudaGetSymbolAddress((void**)&x2,   g_x2);
    cudaGetSymbolAddress((void**)&ik,   g_ik);
    cudaGetSymbolAddress((void**)&ie,   g_ie);
    cudaGetSymbolAddress((void**)&hh,   g_hh);
    cudaGetSymbolAddress((void**)&hl,   g_hl);
    cudaGetSymbolAddress((void**)&wqkvh, g_wqkvh);
    cudaGetSymbolAddress((void**)&wqkvl, g_wqkvl);
    cudaGetSymbolAddress((void**)&wprojh, g_wprojh);
    cudaGetSymbolAddress((void**)&wfc1h, g_wfc1h);
    cudaGetSymbolAddress((void**)&wfc2h, g_wfc2h);
    cudaGetSymbolAddress((void**)&aoh,  g_aoh);
    cudaGetSymbolAddress((void**)&h2h,  g_h2h);
    cudaGetSymbolAddress((void**)&mlph, g_mlph);

    const int PROP_SMEM = (K_ * R_ + R_ * 64) * 4;
    cudaFuncSetAttribute(propagate_kernel, cudaFuncAttributeMaxDynamicSharedMemorySize, PROP_SMEM);
    const int SMEM_SPLIT = (HASZ + HBSZ) * 2 * 4;   // 27136
    const int SMEM_PLAIN = (HASZ + HBSZ) * 4;       // 13568

    // 0. weight packing
    cvtw_pack<1><<<(384 * 2304 + 255) / 256, 256>>>(qkvw, wqkvh, wqkvl, 2304, 384 * 2304);
    cvtw_pack<0><<<(384 * 768 + 255) / 256, 256>>>(projw, wprojh, nullptr, 768, 384 * 768);
    cvtw_pack<0><<<(384 * 3072 + 255) / 256, 256>>>(fc1w, wfc1h, nullptr, 3072, 384 * 3072);
    cvtw_pack<0><<<(1536 * 768 + 255) / 256, 256>>>(fc2w, wfc2h, nullptr, 768, 1536 * 768);

    // 1. LN1 -> packed fp16 hi/lo
    ln_pack_kernel<1><<<B_ * N_, 256>>>(x, n1g, n1b, hh, hl);
    // 2. QKV GEMM (split-fp16: ~21-bit mantissa, rank-safe)
    hgemm_kernel<1, false, false, false, false><<<dim3(18, 197), 256, SMEM_SPLIT>>>(
        hh, hl, wqkvh, wqkvl, nullptr, nullptr, qkv, nullptr, 2304, C_, 2304);
    // 3. scores
    score_kernel<<<dim3(B_ * H_, 4, 4), 256>>>(qkv, attn);
    // 4. softmax
    softmax_kernel<<<(B_ * H_ * N_ + 7) / 8, 256>>>(attn);
    // 5. attn @ V -> packed fp16 ao
    av_kernel<<<dim3(B_ * H_, 4), 256>>>(qkv, attn, aoh);
    // 6. proj + bias + residual (plain fp16)
    hgemm_kernel<0, false, true, true, false><<<dim3(6, 197), 256, SMEM_PLAIN>>>(
        aoh, nullptr, wprojh, nullptr, projb, x, x1, nullptr, C_, C_, C_);
    // 7. selection
    select_kernel<<<B_, 256>>>(attn, ik, ie);
    // 8. propagation
    propagate_kernel<<<B_ * H_, 256, PROP_SMEM>>>(attn, x1, ik, ie, x2);
    // 9. LN2 -> packed fp16
    ln_pack_kernel<0><<<B_ * K_, 256>>>(x2, n2g, n2b, h2h, nullptr);
    // 10. fc1 + gelu -> packed fp16 mlp
    hgemm_kernel<0, true, true, false, true><<<dim3(24, 99), 256, SMEM_PLAIN>>>(
        h2h, nullptr, wfc1h, nullptr, fc1b, nullptr, nullptr, mlph, 4 * C_, C_, 0);
    // 11. fc2 + residual -> out
    hgemm_kernel<0, false, true, true, false><<<dim3(6, 99), 256, SMEM_PLAIN>>>(
        mlph, nullptr, wfc2h, nullptr, fc2b, x2, out, nullptr, C_, 4 * C_, C_);
}

// round 7
// speedup vs baseline: 1.1107x; 1.1107x over previous
#include <cuda_runtime.h>
#include <cuda_fp16.h>
#include <math.h>

#define B_   64
#define N_   197
#define C_   768
#define H_   12
#define R_   98
#define K_   99
#define NKEPT_ 98
#define THRK_ 1941
#define ALPHA_ 0.1f
#define EPS_ 1e-5f
#define BH_  (B_*H_)

// ---------------- scratch ----------------
__device__ float    g_qkv [(size_t)B_*N_*3*C_];
__device__ float    g_attn[(size_t)BH_*N_*N_];
__device__ float    g_x1  [(size_t)B_*N_*C_];
__device__ float    g_x2  [(size_t)B_*K_*C_];
__device__ int      g_ik  [B_*K_];
__device__ int      g_ie  [B_*R_];
__device__ unsigned g_hh  [(size_t)B_*N_*C_/2];
__device__ unsigned g_hl  [(size_t)B_*N_*C_/2];
__device__ unsigned g_wqkvh[(size_t)C_/2*3*C_];
__device__ unsigned g_wqkvl[(size_t)C_/2*3*C_];
__device__ unsigned g_wprojh[(size_t)C_/2*C_];
__device__ unsigned g_wfc1h[(size_t)C_/2*4*C_];
__device__ unsigned g_wfc2h[(size_t)4*C_/2*C_];
__device__ unsigned g_aoh [(size_t)B_*N_*C_/2];
__device__ unsigned g_h2h [(size_t)B_*K_*C_/2];
__device__ unsigned g_mlph[(size_t)B_*K_*4*C_/2];

// ---------------- helpers ----------------
__device__ __forceinline__ unsigned packh2(float a, float b) {
    __half2 h = __floats2half2_rn(a, b);
    return *reinterpret_cast<unsigned*>(&h);
}
__device__ __forceinline__ void splith2(float a, float b, unsigned& hi, unsigned& lo) {
    __half ah = __float2half_rn(a), bh = __float2half_rn(b);
    __half2 h = __halves2half2(ah, bh);
    hi = *reinterpret_cast<unsigned*>(&h);
    lo = packh2(a - __half2float(ah), b - __half2float(bh));
}
__device__ __forceinline__ void mma_f16(float c[4], const unsigned a[4], const unsigned b[2]) {
    asm volatile(
        "mma.sync.aligned.m16n8k16.row.col.f32.f16.f16.f32 "
        "{%0,%1,%2,%3},{%4,%5,%6,%7},{%8,%9},{%0,%1,%2,%3};"
        : "+f"(c[0]), "+f"(c[1]), "+f"(c[2]), "+f"(c[3])
        : "r"(a[0]), "r"(a[1]), "r"(a[2]), "r"(a[3]), "r"(b[0]), "r"(b[1]));
}

// ---------------- weight pack: [K][N] fp32 -> [K/2][N] half2 ----------------
template<int SPLIT>
__global__ void cvtw_pack(const float* __restrict__ w, unsigned* __restrict__ hi,
                          unsigned* __restrict__ lo, int Nd, int totalWords)
{
    int idx = blockIdx.x * 256 + threadIdx.x;
    if (idx >= totalWords) return;
    int kk = idx / Nd, n = idx - kk * Nd;
    float e = w[(size_t)(2 * kk) * Nd + n];
    float o = w[(size_t)(2 * kk + 1) * Nd + n];
    if (SPLIT) { unsigned h, l; splith2(e, o, h, l); hi[idx] = h; lo[idx] = l; }
    else hi[idx] = packh2(e, o);
}

// ---------------- LayerNorm -> packed fp16 hi(/lo) ----------------
template<int SPLIT>
__global__ void ln_pack_kernel(const float* __restrict__ x, const float* __restrict__ g,
                               const float* __restrict__ bta,
                               unsigned* __restrict__ hi, unsigned* __restrict__ lo)
{
    int row = blockIdx.x;
    const float2* xr = (const float2*)(x + (size_t)row * C_);
    int tid = threadIdx.x;
    float2 v1 = xr[tid];
    float2 v2 = make_float2(0.f, 0.f);
    if (tid < 128) v2 = xr[tid + 256];
    float s = v1.x + v1.y + v2.x + v2.y;
    float ss = v1.x * v1.x + v1.y * v1.y + v2.x * v2.x + v2.y * v2.y;
    for (int off = 16; off; off >>= 1) {
        s  += __shfl_xor_sync(0xffffffffu, s, off);
        ss += __shfl_xor_sync(0xffffffffu, ss, off);
    }
    __shared__ float rs[8], rss[8];
    __shared__ float smean, srstd;
    int w = tid >> 5;
    if ((tid & 31) == 0) { rs[w] = s; rss[w] = ss; }
    __syncthreads();
    if (tid == 0) {
        float S = 0.f, SS = 0.f;
        for (int i = 0; i < 8; i++) { S += rs[i]; SS += rss[i]; }
        float mean = S * (1.f / C_);
        float var = SS * (1.f / C_) - mean * mean;
        smean = mean; srstd = rsqrtf(var + EPS_);
    }
    __syncthreads();
    float mean = smean, rstd = srstd;
    size_t base = (size_t)row * (C_ / 2);
#pragma unroll
    for (int p = 0; p < 2; p++) {
        if (p == 1 && tid >= 128) break;
        int wi = tid + p * 256;
        float2 v = (p == 0) ? v1 : v2;
        int c = wi * 2;
        float a = (v.x - mean) * rstd * g[c] + bta[c];
        float b = (v.y - mean) * rstd * g[c + 1] + bta[c + 1];
        if (SPLIT) { unsigned h, l; splith2(a, b, h, l); hi[base + wi] = h; lo[base + wi] = l; }
        else hi[base + wi] = packh2(a, b);
    }
}

// ---------------- fp16 tensor GEMM: 64x128 tiles, k-step 32 ----------------
#define HA_W 20
#define HASZ (64 * HA_W)
#define HBSZ (16 * 132)
template<int SPLIT, bool GELU, bool HASBIAS, bool HASRES, bool OUTPACK>
__global__ void hgemm_kernel(const unsigned* __restrict__ Ah, const unsigned* __restrict__ Al,
                             const unsigned* __restrict__ Bh, const unsigned* __restrict__ Bl,
                             const float* __restrict__ bias, const float* __restrict__ res,
                             float* __restrict__ Cf, unsigned* __restrict__ Cu,
                             int Nd, int Kd, int ldc, int n0ofs)
{
    extern __shared__ unsigned smu[];
    unsigned* AsH = smu;
    unsigned* AsL = AsH + HASZ;
    unsigned* BsH = AsH + HASZ * (1 + SPLIT);
    unsigned* BsL = BsH + HBSZ;

    int tid = threadIdx.x, lane = tid & 31, wid = tid >> 5;
    int wm = wid & 1, wn = wid >> 1;
    int g = lane >> 2, tg = lane & 3;
    int m0 = blockIdx.y * 64, n0 = blockIdx.x * 128 + n0ofs;
    int Kw = Kd / 2;

    float acc[2][4][4];
#pragma unroll
    for (int i = 0; i < 2; i++)
#pragma unroll
        for (int j = 0; j < 4; j++)
#pragma unroll
            for (int q = 0; q < 4; q++) acc[i][j][q] = 0.f;

    int am = tid >> 2, aw = (tid & 3) * 4;
    int bkw = tid >> 5;
    int bn4 = (tid & 31) * 4;

    for (int k0w = 0; k0w < Kw; k0w += 16) {
        uint4 avh = *(const uint4*)&Ah[(size_t)(m0 + am) * Kw + k0w + aw];
        uint4 avl;
        if (SPLIT) avl = *(const uint4*)&Al[(size_t)(m0 + am) * Kw + k0w + aw];
        uint4 bvh0 = *(const uint4*)&Bh[(size_t)(k0w + bkw) * Nd + n0 + bn4];
        uint4 bvh1 = *(const uint4*)&Bh[(size_t)(k0w + bkw + 8) * Nd + n0 + bn4];
        uint4 bvl0, bvl1;
        if (SPLIT) {
            bvl0 = *(const uint4*)&Bl[(size_t)(k0w + bkw) * Nd + n0 + bn4];
            bvl1 = *(const uint4*)&Bl[(size_t)(k0w + bkw + 8) * Nd + n0 + bn4];
        }
        __syncthreads();
        *(uint4*)&AsH[am * HA_W + aw] = avh;
        if (SPLIT) *(uint4*)&AsL[am * HA_W + aw] = avl;
        *(uint4*)&BsH[bkw * 132 + bn4] = bvh0;
        *(uint4*)&BsH[(bkw + 8) * 132 + bn4] = bvh1;
        if (SPLIT) {
            *(uint4*)&BsL[bkw * 132 + bn4] = bvl0;
            *(uint4*)&BsL[(bkw + 8) * 132 + bn4] = bvl1;
        }
        __syncthreads();

        int arow = wm * 32 + g;
#pragma unroll
        for (int s = 0; s < 2; s++) {
            unsigned ah[2][4], al[2][4];
#pragma unroll
            for (int mf = 0; mf < 2; mf++) {
                int base = (arow + mf * 16) * HA_W + s * 8 + tg;
                ah[mf][0] = AsH[base];          ah[mf][1] = AsH[base + 8 * HA_W];
                ah[mf][2] = AsH[base + 4];      ah[mf][3] = AsH[base + 8 * HA_W + 4];
                if (SPLIT) {
                    al[mf][0] = AsL[base];      al[mf][1] = AsL[base + 8 * HA_W];
                    al[mf][2] = AsL[base + 4];  al[mf][3] = AsL[base + 8 * HA_W + 4];
                }
            }
            unsigned bh[4][2], bl[4][2];
#pragma unroll
            for (int nf = 0; nf < 4; nf++) {
                int n = wn * 32 + nf * 8 + g;
                bh[nf][0] = BsH[(s * 8 + tg) * 132 + n];
                bh[nf][1] = BsH[(s * 8 + tg + 4) * 132 + n];
                if (SPLIT) {
                    bl[nf][0] = BsL[(s * 8 + tg) * 132 + n];
                    bl[nf][1] = BsL[(s * 8 + tg + 4) * 132 + n];
                }
            }
#pragma unroll
            for (int mf = 0; mf < 2; mf++)
#pragma unroll
                for (int nf = 0; nf < 4; nf++) {
                    mma_f16(acc[mf][nf], ah[mf], bh[nf]);
                    if (SPLIT) {
                        mma_f16(acc[mf][nf], ah[mf], bl[nf]);
                        mma_f16(acc[mf][nf], al[mf], bh[nf]);
                    }
                }
        }
    }

#pragma unroll
    for (int mf = 0; mf < 2; mf++) {
        int row = m0 + wm * 32 + mf * 16 + g;
#pragma unroll
        for (int nf = 0; nf < 4; nf++) {
            int col = n0 + wn * 32 + nf * 8 + 2 * tg;
            float b0 = 0.f, b1 = 0.f;
            if (HASBIAS) { b0 = bias[col]; b1 = bias[col + 1]; }
#pragma unroll
            for (int half = 0; half < 2; half++) {
                int r = row + half * 8;
                float c0 = acc[mf][nf][half * 2 + 0] + b0;
                float c1 = acc[mf][nf][half * 2 + 1] + b1;
                if (GELU) {
                    c0 = 0.5f * c0 * (1.f + erff(c0 * 0.70710678118654752f));
                    c1 = 0.5f * c1 * (1.f + erff(c1 * 0.70710678118654752f));
                }
                if (OUTPACK) {
                    Cu[(size_t)r * (Nd / 2) + col / 2] = packh2(c0, c1);
                } else {
                    size_t base = (size_t)r * ldc + col;
                    if (HASRES) {
                        float2 rv = *(const float2*)&res[base];
                        c0 += rv.x; c1 += rv.y;
                    }
                    float2 ov; ov.x = c0; ov.y = c1;
                    *(float2*)&Cf[base] = ov;
                }
            }
        }
    }
}

// ---------------- scores: split-fp16 MMA, 64x64 per block ----------------
__global__ void score_mma(const float* __restrict__ qkv, float* __restrict__ attn)
{
    __shared__ unsigned Qh[64 * 36], Ql[64 * 36], Kh[32 * 72], Kl[32 * 72];
    int bh = blockIdx.x, b = bh / H_, hh = bh % H_;
    int m0 = blockIdx.y * 64, n0 = blockIdx.z * 64;
    int tid = threadIdx.x, lane = tid & 31, wid = tid >> 5;
    int g = lane >> 2, tg = lane & 3;
    int wm = wid & 3, wn = wid >> 2;

#pragma unroll
    for (int r = 0; r < 8; r++) {
        int idx = tid + r * 256;
        int row = idx >> 5, kw = idx & 31;
        int mq = m0 + row, nk = n0 + row;
        float2 qv = make_float2(0.f, 0.f), kv = make_float2(0.f, 0.f);
        if (mq < N_) qv = *(const float2*)&qkv[(size_t)(b * N_ + mq) * 2304 + hh * 64 + 2 * kw];
        if (nk < N_) kv = *(const float2*)&qkv[(size_t)(b * N_ + nk) * 2304 + 768 + hh * 64 + 2 * kw];
        unsigned h, l;
        splith2(qv.x * 0.125f, qv.y * 0.125f, h, l);
        Qh[row * 36 + kw] = h; Ql[row * 36 + kw] = l;
        splith2(kv.x, kv.y, h, l);
        Kh[kw * 72 + row] = h; Kl[kw * 72 + row] = l;
    }
    __syncthreads();

    float acc[4][4];
#pragma unroll
    for (int i = 0; i < 4; i++)
#pragma unroll
        for (int j = 0; j < 4; j++) acc[i][j] = 0.f;

#pragma unroll
    for (int s = 0; s < 4; s++) {
        int abase = (wm * 16 + g) * 36 + s * 8 + tg;
        unsigned ah[4] = {Qh[abase], Qh[abase + 8 * 36], Qh[abase + 4], Qh[abase + 8 * 36 + 4]};
        unsigned al[4] = {Ql[abase], Ql[abase + 8 * 36], Ql[abase + 4], Ql[abase + 8 * 36 + 4]};
#pragma unroll
        for (int nf = 0; nf < 4; nf++) {
            int n = wn * 32 + nf * 8 + g;
            unsigned bhf[2] = {Kh[(s * 8 + tg) * 72 + n], Kh[(s * 8 + tg + 4) * 72 + n]};
            unsigned blf[2] = {Kl[(s * 8 + tg) * 72 + n], Kl[(s * 8 + tg + 4) * 72 + n]};
            mma_f16(acc[nf], ah, bhf);
            mma_f16(acc[nf], ah, blf);
            mma_f16(acc[nf], al, bhf);
        }
    }
#pragma unroll
    for (int nf = 0; nf < 4; nf++) {
        int col = n0 + wn * 32 + nf * 8 + 2 * tg;
#pragma unroll
        for (int hf = 0; hf < 2; hf++) {
            int row = m0 + wm * 16 + g + hf * 8;
            if (row < N_) {
                float* arow = attn + ((size_t)bh * N_ + row) * N_;
                if (col < N_)     arow[col]     = acc[nf][hf * 2 + 0];
                if (col + 1 < N_) arow[col + 1] = acc[nf][hf * 2 + 1];
            }
        }
    }
}

// ---------------- AV: plain-fp16 MMA, 64x64 per block ----------------
__global__ void av_mma(const float* __restrict__ attn, const float* __restrict__ qkv,
                       unsigned* __restrict__ aoh)
{
    __shared__ unsigned As[64 * 20], Vs[32 * 72];
    int bh = blockIdx.x, b = bh / H_, hh = bh % H_;
    int m0 = blockIdx.y * 64;
    int tid = threadIdx.x, lane = tid & 31, wid = tid >> 5;
    int g = lane >> 2, tg = lane & 3;
    int wm = wid & 3, wn = wid >> 2;

    float acc[4][4];
#pragma unroll
    for (int i = 0; i < 4; i++)
#pragma unroll
        for (int j = 0; j < 4; j++) acc[i][j] = 0.f;

    for (int k0 = 0; k0 < 224; k0 += 32) {
        __syncthreads();
#pragma unroll
        for (int r = 0; r < 4; r++) {
            int idx = tid + r * 256;
            int m = idx >> 4, kw = idx & 15;
            int mg = m0 + m, t0 = k0 + 2 * kw;
            float a0 = 0.f, a1 = 0.f;
            if (mg < N_) {
                const float* arow = attn + ((size_t)bh * N_ + mg) * N_;
                if (t0 < N_)     a0 = arow[t0];
                if (t0 + 1 < N_) a1 = arow[t0 + 1];
            }
            As[m * 20 + kw] = packh2(a0, a1);
        }
#pragma unroll
        for (int r = 0; r < 4; r++) {
            int idx = tid + r * 256;
            int kw = idx >> 6, n = idx & 63;
            int t0 = k0 + 2 * kw;
            float v0 = 0.f, v1 = 0.f;
            if (t0 < N_)     v0 = qkv[(size_t)(b * N_ + t0) * 2304 + 1536 + hh * 64 + n];
            if (t0 + 1 < N_) v1 = qkv[(size_t)(b * N_ + t0 + 1) * 2304 + 1536 + hh * 64 + n];
            Vs[kw * 72 + n] = packh2(v0, v1);
        }
        __syncthreads();
#pragma unroll
        for (int s = 0; s < 2; s++) {
            int abase = (wm * 16 + g) * 20 + s * 8 + tg;
            unsigned ah[4] = {As[abase], As[abase + 8 * 20], As[abase + 4], As[abase + 8 * 20 + 4]};
#pragma unroll
            for (int nf = 0; nf < 4; nf++) {
                int n = wn * 32 + nf * 8 + g;
                unsigned bf[2] = {Vs[(s * 8 + tg) * 72 + n], Vs[(s * 8 + tg + 4) * 72 + n]};
                mma_f16(acc[nf], ah, bf);
            }
        }
    }
#pragma unroll
    for (int nf = 0; nf < 4; nf++) {
        int col = wn * 32 + nf * 8 + 2 * tg;
#pragma unroll
        for (int hf = 0; hf < 2; hf++) {
            int m = m0 + wm * 16 + g + hf * 8;
            if (m < N_)
                aoh[(size_t)(b * N_ + m) * 384 + (hh * 64 + col) / 2] =
                    packh2(acc[nf][hf * 2 + 0], acc[nf][hf * 2 + 1]);
        }
    }
}

// ---------------- softmax ----------------
__global__ void softmax_kernel(float* __restrict__ attn)
{
    int row = blockIdx.x * 8 + (threadIdx.x >> 5);
    if (row >= BH_ * N_) return;
    int lane = threadIdx.x & 31;
    float* arow = attn + (size_t)row * N_;
    float v[7];
    float mx = -1e30f;
#pragma unroll
    for (int c = 0; c < 7; c++) {
        int j = lane + c * 32;
        v[c] = (j < N_) ? arow[j] : -1e30f;
        mx = fmaxf(mx, v[c]);
    }
    for (int off = 16; off; off >>= 1) mx = fmaxf(mx, __shfl_xor_sync(0xffffffffu, mx, off));
    float sum = 0.f;
#pragma unroll
    for (int c = 0; c < 7; c++) { float e = expf(v[c] - mx); v[c] = e; sum += e; }
    for (int off = 16; off; off >>= 1) sum += __shfl_xor_sync(0xffffffffu, sum, off);
    float inv = 1.f / sum;
#pragma unroll
    for (int c = 0; c < 7; c++) {
        int j = lane + c * 32;
        if (j < N_) arow[j] = v[c] * inv;
    }
}

// ---------------- selection ----------------
__global__ void select_kernel(const float* __restrict__ attn, int* __restrict__ ik,
                              int* __restrict__ ie)
{
    __shared__ float diag[196];
    __shared__ int kept[196];
    int b = blockIdx.x, tid = threadIdx.x;
    if (tid < 196) {
        float s = 0.f;
        for (int hh = 0; hh < H_; hh++)
            s += attn[((size_t)(b * H_ + hh) * N_ + (tid + 1)) * N_ + (tid + 1)];
        diag[tid] = s;
    }
    __syncthreads();
    if (tid < 196) {
        float di = diag[tid];
        int rank = 0;
        for (int j = 0; j < 196; j++) {
            float dj = diag[j];
            rank += (dj > di) || (dj == di && j < tid);
        }
        kept[tid] = (rank < NKEPT_) ? 1 : 0;
    }
    __syncthreads();
    if (tid < 196) {
        int mine = kept[tid];
        int pos = 0;
        for (int j = 0; j < tid; j++) pos += (kept[j] == mine);
        if (mine) ik[b * K_ + 1 + pos] = tid + 1;
        else      ie[b * R_ + pos]     = tid + 1;
    }
    if (tid == 0) ik[b * K_] = 0;
}

// ---------------- propagation ----------------
__global__ void propagate_kernel(const float* __restrict__ attn, const float* __restrict__ x1,
                                 const int* __restrict__ ikg, const int* __restrict__ ieg,
                                 float* __restrict__ x2)
{
    extern __shared__ float sm[];
    float* ws = sm;
    float* xe = sm + K_ * R_;
    __shared__ int ik[K_], ie[R_];
    __shared__ int cnt;
    int bh = blockIdx.x;
    int b = bh / H_, hh = bh % H_;
    int tid = threadIdx.x;
    if (tid < K_) ik[tid] = ikg[b * K_ + tid];
    if (tid < R_) ie[tid] = ieg[b * R_ + tid];
    __syncthreads();
    const float* ablk = attn + (size_t)bh * N_ * N_;
    for (int idx = tid; idx < K_ * R_; idx += 256) {
        int k = idx / R_, e = idx - k * R_;
        ws[idx] = ablk[(size_t)ik[k] * N_ + ie[e]];
    }
    for (int idx = tid; idx < R_ * 64; idx += 256) {
        int e = idx >> 6, d = idx & 63;
        xe[idx] = x1[(size_t)(b * N_ + ie[e]) * 768 + hh * 64 + d];
    }
    __syncthreads();

    unsigned lo = 0u, hi = 0x7f7fffffu;
    while (lo < hi) {
        unsigned mid = lo + ((hi - lo + 1) >> 1);
        if (tid == 0) cnt = 0;
        __syncthreads();
        int local = 0;
        for (int i = tid; i < K_ * R_; i += 256)
            local += (__float_as_uint(ws[i]) >= mid);
        for (int off = 16; off; off >>= 1) local += __shfl_xor_sync(0xffffffffu, local, off);
        if ((tid & 31) == 0) atomicAdd(&cnt, local);
        __syncthreads();
        int c = cnt;
        __syncthreads();
        if (c >= THRK_) lo = mid; else hi = mid - 1;
    }
    float thr = __uint_as_float(lo);

    for (int p = tid; p < K_ * 64; p += 256) {
        int k = p >> 6, d = p & 63;
        const float* wr = ws + k * R_;
        float acc = 0.f;
#pragma unroll 2
        for (int e = 0; e < R_; e++) {
            float wv = wr[e];
            wv = (wv >= thr) ? wv : 0.f;
            acc = fmaf(wv, xe[e * 64 + d], acc);
        }
        x2[(size_t)(b * K_ + k) * 768 + hh * 64 + d] =
            x1[(size_t)(b * N_ + ik[k]) * 768 + hh * 64 + d] + ALPHA_ * acc;
    }
}

// ---------------- host ----------------
extern "C" void kernel_launch(void* const* d_in, const int* in_sizes, int n_in,
                              void* d_out, int out_size)
{
    const float* x     = (const float*)d_in[0];
    const float* n1g   = (const float*)d_in[1];
    const float* n1b   = (const float*)d_in[2];
    const float* qkvw  = (const float*)d_in[3];
    const float* projw = (const float*)d_in[4];
    const float* projb = (const float*)d_in[5];
    const float* n2g   = (const float*)d_in[6];
    const float* n2b   = (const float*)d_in[7];
    const float* fc1w  = (const float*)d_in[8];
    const float* fc1b  = (const float*)d_in[9];
    const float* fc2w  = (const float*)d_in[10];
    const float* fc2b  = (const float*)d_in[11];
    float* out = (float*)d_out;

    float *qkv, *attn, *x1, *x2;
    int *ik, *ie;
    unsigned *hh, *hl, *wqkvh, *wqkvl, *wprojh, *wfc1h, *wfc2h, *aoh, *h2h, *mlph;
    cudaGetSymbolAddress((void**)&qkv,  g_qkv);
    cudaGetSymbolAddress((void**)&attn, g_attn);
    cudaGetSymbolAddress((void**)&x1,   g_x1);
    cudaGetSymbolAddress((void**)&x2,   g_x2);
    cudaGetSymbolAddress((void**)&ik,   g_ik);
    cudaGetSymbolAddress((void**)&ie,   g_ie);
    cudaGetSymbolAddress((void**)&hh,   g_hh);
    cudaGetSymbolAddress((void**)&hl,   g_hl);
    cudaGetSymbolAddress((void**)&wqkvh, g_wqkvh);
    cudaGetSymbolAddress((void**)&wqkvl, g_wqkvl);
    cudaGetSymbolAddress((void**)&wprojh, g_wprojh);
    cudaGetSymbolAddress((void**)&wfc1h, g_wfc1h);
    cudaGetSymbolAddress((void**)&wfc2h, g_wfc2h);
    cudaGetSymbolAddress((void**)&aoh,  g_aoh);
    cudaGetSymbolAddress((void**)&h2h,  g_h2h);
    cudaGetSymbolAddress((void**)&mlph, g_mlph);

    const int PROP_SMEM = (K_ * R_ + R_ * 64) * 4;
    cudaFuncSetAttribute(propagate_kernel, cudaFuncAttributeMaxDynamicSharedMemorySize, PROP_SMEM);
    const int SMEM_SPLIT = (HASZ + HBSZ) * 2 * 4;
    const int SMEM_PLAIN = (HASZ + HBSZ) * 4;

    // 0. weight packing
    cvtw_pack<1><<<(384 * 2304 + 255) / 256, 256>>>(qkvw, wqkvh, wqkvl, 2304, 384 * 2304);
    cvtw_pack<0><<<(384 * 768 + 255) / 256, 256>>>(projw, wprojh, nullptr, 768, 384 * 768);
    cvtw_pack<0><<<(384 * 3072 + 255) / 256, 256>>>(fc1w, wfc1h, nullptr, 3072, 384 * 3072);
    cvtw_pack<0><<<(1536 * 768 + 255) / 256, 256>>>(fc2w, wfc2h, nullptr, 768, 1536 * 768);

    // 1. LN1 -> packed fp16 hi/lo
    ln_pack_kernel<1><<<B_ * N_, 256>>>(x, n1g, n1b, hh, hl);
    // 2a. QK columns [0,1536) split-fp16 (rank-safe)
    hgemm_kernel<1, false, false, false, false><<<dim3(12, 197), 256, SMEM_SPLIT>>>(
        hh, hl, wqkvh, wqkvl, nullptr, nullptr, qkv, nullptr, 2304, C_, 2304, 0);
    // 2b. V columns [1536,2304) plain fp16
    hgemm_kernel<0, false, false, false, false><<<dim3(6, 197), 256, SMEM_PLAIN>>>(
        hh, nullptr, wqkvh, nullptr, nullptr, nullptr, qkv, nullptr, 2304, C_, 2304, 1536);
    // 3. scores (split-fp16 MMA)
    score_mma<<<dim3(BH_, 4, 4), 256>>>(qkv, attn);
    // 4. softmax
    softmax_kernel<<<(BH_ * N_ + 7) / 8, 256>>>(attn);
    // 5. attn @ V (fp16 MMA) -> packed fp16 ao
    av_mma<<<dim3(BH_, 4), 256>>>(attn, qkv, aoh);
    // 6. proj + bias + residual
    hgemm_kernel<0, false, true, true, false><<<dim3(6, 197), 256, SMEM_PLAIN>>>(
        aoh, nullptr, wprojh, nullptr, projb, x, x1, nullptr, C_, C_, C_, 0);
    // 7. selection
    select_kernel<<<B_, 256>>>(attn, ik, ie);
    // 8. propagation
    propagate_kernel<<<BH_, 256, PROP_SMEM>>>(attn, x1, ik, ie, x2);
    // 9. LN2 -> packed fp16
    ln_pack_kernel<0><<<B_ * K_, 256>>>(x2, n2g, n2b, h2h, nullptr);
    // 10. fc1 + gelu -> packed fp16
    hgemm_kernel<0, true, true, false, true><<<dim3(24, 99), 256, SMEM_PLAIN>>>(
        h2h, nullptr, wfc1h, nullptr, fc1b, nullptr, nullptr, mlph, 4 * C_, C_, 0, 0);
    // 11. fc2 + residual -> out
    hgemm_kernel<0, false, true, true, false><<<dim3(6, 99), 256, SMEM_PLAIN>>>(
        mlph, nullptr, wfc2h, nullptr, fc2b, x2, out, nullptr, C_, 4 * C_, C_, 0);
}

// round 8
// speedup vs baseline: 1.2456x; 1.1215x over previous
#include <cuda_runtime.h>
#include <cuda_fp16.h>
#include <math.h>

#define B_   64
#define N_   197
#define C_   768
#define H_   12
#define R_   98
#define K_   99
#define NKEPT_ 98
#define THRK_ 1941
#define ALPHA_ 0.1f
#define EPS_ 1e-5f
#define BH_  (B_*H_)

// ---------------- scratch ----------------
__device__ float    g_qkv [(size_t)B_*N_*3*C_];
__device__ float    g_attn[(size_t)BH_*N_*N_];
__device__ float    g_x1  [(size_t)B_*N_*C_];
__device__ float    g_x2  [(size_t)B_*K_*C_];
__device__ int      g_ik  [B_*K_];
__device__ int      g_ie  [B_*R_];
__device__ unsigned g_hh  [(size_t)B_*N_*C_/2];   // packed half2 along K == half [M][K]
__device__ unsigned g_hl  [(size_t)B_*N_*C_/2];
__device__ __half   g_wqkvh[(size_t)C_*3*C_];     // plain half [K][N]
__device__ __half   g_wqkvl[(size_t)C_*3*C_];
__device__ __half   g_wprojh[(size_t)C_*C_];
__device__ __half   g_wfc1h[(size_t)C_*4*C_];
__device__ __half   g_wfc2h[(size_t)4*C_*C_];
__device__ unsigned g_aoh [(size_t)B_*N_*C_/2];
__device__ unsigned g_h2h [(size_t)B_*K_*C_/2];
__device__ unsigned g_mlph[(size_t)B_*K_*4*C_/2];

// ---------------- helpers ----------------
__device__ __forceinline__ unsigned packh2(float a, float b) {
    __half2 h = __floats2half2_rn(a, b);
    return *reinterpret_cast<unsigned*>(&h);
}
__device__ __forceinline__ void splith2(float a, float b, unsigned& hi, unsigned& lo) {
    __half ah = __float2half_rn(a), bh = __float2half_rn(b);
    __half2 h = __halves2half2(ah, bh);
    hi = *reinterpret_cast<unsigned*>(&h);
    lo = packh2(a - __half2float(ah), b - __half2float(bh));
}
__device__ __forceinline__ unsigned sm_u32(const void* p) {
    return (unsigned)__cvta_generic_to_shared(p);
}
__device__ __forceinline__ void ldsm4(unsigned r[4], unsigned a) {
    asm volatile("ldmatrix.sync.aligned.m8n8.x4.shared.b16 {%0,%1,%2,%3}, [%4];"
                 : "=r"(r[0]), "=r"(r[1]), "=r"(r[2]), "=r"(r[3]) : "r"(a));
}
__device__ __forceinline__ void ldsm4t(unsigned r[4], unsigned a) {
    asm volatile("ldmatrix.sync.aligned.m8n8.x4.trans.shared.b16 {%0,%1,%2,%3}, [%4];"
                 : "=r"(r[0]), "=r"(r[1]), "=r"(r[2]), "=r"(r[3]) : "r"(a));
}
__device__ __forceinline__ void mma_f16(float c[4], const unsigned a[4], const unsigned b[2]) {
    asm volatile(
        "mma.sync.aligned.m16n8k16.row.col.f32.f16.f16.f32 "
        "{%0,%1,%2,%3},{%4,%5,%6,%7},{%8,%9},{%0,%1,%2,%3};"
        : "+f"(c[0]), "+f"(c[1]), "+f"(c[2]), "+f"(c[3])
        : "r"(a[0]), "r"(a[1]), "r"(a[2]), "r"(a[3]), "r"(b[0]), "r"(b[1]));
}

// ---------------- weight convert: fp32 [K][N] -> half [K][N] (hi, opt lo) ----------
template<int SPLIT>
__global__ void cvtw_h(const float* __restrict__ w, __half* __restrict__ hi,
                       __half* __restrict__ lo, int n)
{
    int i = (blockIdx.x * 256 + threadIdx.x) * 8;
    if (i >= n) return;
    float4 a = *(const float4*)&w[i];
    float4 b = *(const float4*)&w[i + 4];
    __half2 h[4];
    h[0] = __floats2half2_rn(a.x, a.y); h[1] = __floats2half2_rn(a.z, a.w);
    h[2] = __floats2half2_rn(b.x, b.y); h[3] = __floats2half2_rn(b.z, b.w);
    *(uint4*)&hi[i] = *(uint4*)h;
    if (SPLIT) {
        __half2 l[4];
        l[0] = __floats2half2_rn(a.x - __low2float(h[0]), a.y - __high2float(h[0]));
        l[1] = __floats2half2_rn(a.z - __low2float(h[1]), a.w - __high2float(h[1]));
        l[2] = __floats2half2_rn(b.x - __low2float(h[2]), b.y - __high2float(h[2]));
        l[3] = __floats2half2_rn(b.z - __low2float(h[3]), b.w - __high2float(h[3]));
        *(uint4*)&lo[i] = *(uint4*)l;
    }
}

// ---------------- LayerNorm -> packed fp16 hi(/lo) ----------------
template<int SPLIT>
__global__ void ln_pack_kernel(const float* __restrict__ x, const float* __restrict__ g,
                               const float* __restrict__ bta,
                               unsigned* __restrict__ hi, unsigned* __restrict__ lo)
{
    int row = blockIdx.x;
    const float2* xr = (const float2*)(x + (size_t)row * C_);
    int tid = threadIdx.x;
    float2 v1 = xr[tid];
    float2 v2 = make_float2(0.f, 0.f);
    if (tid < 128) v2 = xr[tid + 256];
    float s = v1.x + v1.y + v2.x + v2.y;
    float ss = v1.x * v1.x + v1.y * v1.y + v2.x * v2.x + v2.y * v2.y;
    for (int off = 16; off; off >>= 1) {
        s  += __shfl_xor_sync(0xffffffffu, s, off);
        ss += __shfl_xor_sync(0xffffffffu, ss, off);
    }
    __shared__ float rs[8], rss[8];
    __shared__ float smean, srstd;
    int w = tid >> 5;
    if ((tid & 31) == 0) { rs[w] = s; rss[w] = ss; }
    __syncthreads();
    if (tid == 0) {
        float S = 0.f, SS = 0.f;
        for (int i = 0; i < 8; i++) { S += rs[i]; SS += rss[i]; }
        float mean = S * (1.f / C_);
        float var = SS * (1.f / C_) - mean * mean;
        smean = mean; srstd = rsqrtf(var + EPS_);
    }
    __syncthreads();
    float mean = smean, rstd = srstd;
    size_t base = (size_t)row * (C_ / 2);
#pragma unroll
    for (int p = 0; p < 2; p++) {
        if (p == 1 && tid >= 128) break;
        int wi = tid + p * 256;
        float2 v = (p == 0) ? v1 : v2;
        int c = wi * 2;
        float a = (v.x - mean) * rstd * g[c] + bta[c];
        float b = (v.y - mean) * rstd * g[c + 1] + bta[c + 1];
        if (SPLIT) { unsigned h, l; splith2(a, b, h, l); hi[base + wi] = h; lo[base + wi] = l; }
        else hi[base + wi] = packh2(a, b);
    }
}

// ---------------- fp16 GEMM: 64x128 tile, k32 steps, ldmatrix, double-buffered ----
#define AST 40                    // halves per A shared row
#define BST 136                   // halves per B shared row
#define ABUF (64 * AST)           // halves
#define BBUF (32 * BST)

template<int SPLIT>
__device__ __forceinline__ void hg_compute(const __half* buf, const int aoff[2],
                                           const int boff[2], float acc[2][4][4])
{
    const __half* AsH = buf;
    const __half* AsL = buf + ABUF;
    const __half* BsH = buf + ABUF * (1 + SPLIT);
    const __half* BsL = BsH + BBUF;
#pragma unroll
    for (int s = 0; s < 2; s++) {
        unsigned ah[2][4], al[2][4];
#pragma unroll
        for (int mf = 0; mf < 2; mf++) {
            ldsm4(ah[mf], sm_u32(AsH + aoff[mf] + s * 16));
            if (SPLIT) ldsm4(al[mf], sm_u32(AsL + aoff[mf] + s * 16));
        }
        unsigned bhf[4][2], blf[4][2];
#pragma unroll
        for (int p = 0; p < 2; p++) {
            unsigned r[4];
            ldsm4t(r, sm_u32(BsH + boff[p] + s * 16 * BST));
            bhf[2*p][0] = r[0]; bhf[2*p][1] = r[1];
            bhf[2*p+1][0] = r[2]; bhf[2*p+1][1] = r[3];
            if (SPLIT) {
                unsigned rl[4];
                ldsm4t(rl, sm_u32(BsL + boff[p] + s * 16 * BST));
                blf[2*p][0] = rl[0]; blf[2*p][1] = rl[1];
                blf[2*p+1][0] = rl[2]; blf[2*p+1][1] = rl[3];
            }
        }
#pragma unroll
        for (int mf = 0; mf < 2; mf++)
#pragma unroll
            for (int nf = 0; nf < 4; nf++) {
                mma_f16(acc[mf][nf], ah[mf], bhf[nf]);
                if (SPLIT) {
                    mma_f16(acc[mf][nf], ah[mf], blf[nf]);
                    mma_f16(acc[mf][nf], al[mf], bhf[nf]);
                }
            }
    }
}

template<int SPLIT, bool GELU, bool HASBIAS, bool HASRES, bool OUTPACK>
__global__ void hgemm_kernel(const unsigned* __restrict__ Ah, const unsigned* __restrict__ Al,
                             const __half* __restrict__ Bh, const __half* __restrict__ Bl,
                             const float* __restrict__ bias, const float* __restrict__ res,
                             float* __restrict__ Cf, unsigned* __restrict__ Cu,
                             int Nd, int Kd, int ldc, int n0ofs)
{
    extern __shared__ __half sh[];
    const int UNIT = (ABUF + BBUF) * (1 + SPLIT);
    int tid = threadIdx.x, lane = tid & 31, wid = tid >> 5;
    int wm = wid & 1, wn = wid >> 1;
    int g = lane >> 2, tg = lane & 3;
    int m0 = blockIdx.y * 64, n0 = blockIdx.x * 128 + n0ofs;
    int Kw = Kd / 2;

    float acc[2][4][4];
#pragma unroll
    for (int i = 0; i < 2; i++)
#pragma unroll
        for (int j = 0; j < 4; j++)
#pragma unroll
            for (int q = 0; q < 4; q++) acc[i][j][q] = 0.f;

    int ar = tid >> 2, agw = (tid & 3) * 4;          // A: word row/col
    int bkr = tid >> 4, bn8 = (tid & 15) * 8;        // B: half row/col
    const unsigned* ApH = Ah + (size_t)(m0 + ar) * Kw + agw;
    const unsigned* ApL = SPLIT ? Al + (size_t)(m0 + ar) * Kw + agw : ApH;
    const __half* BpH0 = Bh + (size_t)bkr * Nd + n0 + bn8;
    const __half* BpH1 = Bh + (size_t)(bkr + 16) * Nd + n0 + bn8;
    const __half* BpL0 = SPLIT ? Bl + (size_t)bkr * Nd + n0 + bn8 : BpH0;
    const __half* BpL1 = SPLIT ? Bl + (size_t)(bkr + 16) * Nd + n0 + bn8 : BpH1;

    int aSts = ar * AST + (tid & 3) * 8;             // halves
    int bSts0 = bkr * BST + bn8, bSts1 = (bkr + 16) * BST + bn8;

    int aoff[2], boff[2];
#pragma unroll
    for (int mf = 0; mf < 2; mf++)
        aoff[mf] = (wm * 32 + mf * 16 + (lane & 15)) * AST + (lane >> 4) * 8;
#pragma unroll
    for (int p = 0; p < 2; p++)
        boff[p] = (lane & 15) * BST + wn * 32 + p * 16 + (lane >> 4) * 8;

    uint4 rah, ral, rb0, rb1, rc0, rc1;
    rah = *(const uint4*)ApH;
    if (SPLIT) ral = *(const uint4*)ApL;
    rb0 = *(const uint4*)BpH0; rb1 = *(const uint4*)BpH1;
    if (SPLIT) { rc0 = *(const uint4*)BpL0; rc1 = *(const uint4*)BpL1; }
    {
        __half* buf = sh;
        *(uint4*)&buf[aSts] = rah;
        if (SPLIT) *(uint4*)&buf[ABUF + aSts] = ral;
        __half* bb = buf + ABUF * (1 + SPLIT);
        *(uint4*)&bb[bSts0] = rb0; *(uint4*)&bb[bSts1] = rb1;
        if (SPLIT) { *(uint4*)&bb[BBUF + bSts0] = rc0; *(uint4*)&bb[BBUF + bSts1] = rc1; }
    }
    __syncthreads();

    int nit = Kd / 32;
    for (int it = 1; it < nit; it++) {
        rah = *(const uint4*)(ApH + it * 16);
        if (SPLIT) ral = *(const uint4*)(ApL + it * 16);
        rb0 = *(const uint4*)(BpH0 + (size_t)it * 32 * Nd);
        rb1 = *(const uint4*)(BpH1 + (size_t)it * 32 * Nd);
        if (SPLIT) {
            rc0 = *(const uint4*)(BpL0 + (size_t)it * 32 * Nd);
            rc1 = *(const uint4*)(BpL1 + (size_t)it * 32 * Nd);
        }
        hg_compute<SPLIT>(sh + ((it - 1) & 1) * UNIT, aoff, boff, acc);
        {
            __half* buf = sh + (it & 1) * UNIT;
            *(uint4*)&buf[aSts] = rah;
            if (SPLIT) *(uint4*)&buf[ABUF + aSts] = ral;
            __half* bb = buf + ABUF * (1 + SPLIT);
            *(uint4*)&bb[bSts0] = rb0; *(uint4*)&bb[bSts1] = rb1;
            if (SPLIT) { *(uint4*)&bb[BBUF + bSts0] = rc0; *(uint4*)&bb[BBUF + bSts1] = rc1; }
        }
        __syncthreads();
    }
    hg_compute<SPLIT>(sh + ((nit - 1) & 1) * UNIT, aoff, boff, acc);

    // epilogue
#pragma unroll
    for (int mf = 0; mf < 2; mf++) {
        int row = m0 + wm * 32 + mf * 16 + g;
#pragma unroll
        for (int nf = 0; nf < 4; nf++) {
            int col = n0 + wn * 32 + nf * 8 + 2 * tg;
            float b0 = 0.f, b1 = 0.f;
            if (HASBIAS) { b0 = bias[col]; b1 = bias[col + 1]; }
#pragma unroll
            for (int half = 0; half < 2; half++) {
                int r = row + half * 8;
                float c0 = acc[mf][nf][half * 2 + 0] + b0;
                float c1 = acc[mf][nf][half * 2 + 1] + b1;
                if (GELU) {
                    c0 = 0.5f * c0 * (1.f + erff(c0 * 0.70710678118654752f));
                    c1 = 0.5f * c1 * (1.f + erff(c1 * 0.70710678118654752f));
                }
                if (OUTPACK) {
                    Cu[(size_t)r * (Nd / 2) + col / 2] = packh2(c0, c1);
                } else {
                    size_t base = (size_t)r * ldc + col;
                    if (HASRES) {
                        float2 rv = *(const float2*)&res[base];
                        c0 += rv.x; c1 += rv.y;
                    }
                    float2 ov; ov.x = c0; ov.y = c1;
                    *(float2*)&Cf[base] = ov;
                }
            }
        }
    }
}

// ---------------- scores: split-fp16 MMA, 64x64 per block ----------------
__global__ void score_mma(const float* __restrict__ qkv, float* __restrict__ attn)
{
    __shared__ unsigned Qh[64 * 36], Ql[64 * 36], Kh[32 * 72], Kl[32 * 72];
    int bh = blockIdx.x, b = bh / H_, hh = bh % H_;
    int m0 = blockIdx.y * 64, n0 = blockIdx.z * 64;
    int tid = threadIdx.x, lane = tid & 31, wid = tid >> 5;
    int g = lane >> 2, tg = lane & 3;
    int wm = wid & 3, wn = wid >> 2;

#pragma unroll
    for (int r = 0; r < 8; r++) {
        int idx = tid + r * 256;
        int row = idx >> 5, kw = idx & 31;
        int mq = m0 + row, nk = n0 + row;
        float2 qv = make_float2(0.f, 0.f), kv = make_float2(0.f, 0.f);
        if (mq < N_) qv = *(const float2*)&qkv[(size_t)(b * N_ + mq) * 2304 + hh * 64 + 2 * kw];
        if (nk < N_) kv = *(const float2*)&qkv[(size_t)(b * N_ + nk) * 2304 + 768 + hh * 64 + 2 * kw];
        unsigned h, l;
        splith2(qv.x * 0.125f, qv.y * 0.125f, h, l);
        Qh[row * 36 + kw] = h; Ql[row * 36 + kw] = l;
        splith2(kv.x, kv.y, h, l);
        Kh[kw * 72 + row] = h; Kl[kw * 72 + row] = l;
    }
    __syncthreads();

    float acc[4][4];
#pragma unroll
    for (int i = 0; i < 4; i++)
#pragma unroll
        for (int j = 0; j < 4; j++) acc[i][j] = 0.f;

#pragma unroll
    for (int s = 0; s < 4; s++) {
        int abase = (wm * 16 + g) * 36 + s * 8 + tg;
        unsigned ah[4] = {Qh[abase], Qh[abase + 8 * 36], Qh[abase + 4], Qh[abase + 8 * 36 + 4]};
        unsigned al[4] = {Ql[abase], Ql[abase + 8 * 36], Ql[abase + 4], Ql[abase + 8 * 36 + 4]};
#pragma unroll
        for (int nf = 0; nf < 4; nf++) {
            int n = wn * 32 + nf * 8 + g;
            unsigned bhf[2] = {Kh[(s * 8 + tg) * 72 + n], Kh[(s * 8 + tg + 4) * 72 + n]};
            unsigned blf[2] = {Kl[(s * 8 + tg) * 72 + n], Kl[(s * 8 + tg + 4) * 72 + n]};
            mma_f16(acc[nf], ah, bhf);
            mma_f16(acc[nf], ah, blf);
            mma_f16(acc[nf], al, bhf);
        }
    }
#pragma unroll
    for (int nf = 0; nf < 4; nf++) {
        int col = n0 + wn * 32 + nf * 8 + 2 * tg;
#pragma unroll
        for (int hf = 0; hf < 2; hf++) {
            int row = m0 + wm * 16 + g + hf * 8;
            if (row < N_) {
                float* arow = attn + ((size_t)bh * N_ + row) * N_;
                if (col < N_)     arow[col]     = acc[nf][hf * 2 + 0];
                if (col + 1 < N_) arow[col + 1] = acc[nf][hf * 2 + 1];
            }
        }
    }
}

// ---------------- AV: plain-fp16 MMA, 64x64 per block ----------------
__global__ void av_mma(const float* __restrict__ attn, const float* __restrict__ qkv,
                       unsigned* __restrict__ aoh)
{
    __shared__ unsigned As[64 * 20], Vs[32 * 72];
    int bh = blockIdx.x, b = bh / H_, hh = bh % H_;
    int m0 = blockIdx.y * 64;
    int tid = threadIdx.x, lane = tid & 31, wid = tid >> 5;
    int g = lane >> 2, tg = lane & 3;
    int wm = wid & 3, wn = wid >> 2;

    float acc[4][4];
#pragma unroll
    for (int i = 0; i < 4; i++)
#pragma unroll
        for (int j = 0; j < 4; j++) acc[i][j] = 0.f;

    for (int k0 = 0; k0 < 224; k0 += 32) {
        __syncthreads();
#pragma unroll
        for (int r = 0; r < 4; r++) {
            int idx = tid + r * 256;
            int m = idx >> 4, kw = idx & 15;
            int mg = m0 + m, t0 = k0 + 2 * kw;
            float a0 = 0.f, a1 = 0.f;
            if (mg < N_) {
                const float* arow = attn + ((size_t)bh * N_ + mg) * N_;
                if (t0 < N_)     a0 = arow[t0];
                if (t0 + 1 < N_) a1 = arow[t0 + 1];
            }
            As[m * 20 + kw] = packh2(a0, a1);
        }
#pragma unroll
        for (int r = 0; r < 4; r++) {
            int idx = tid + r * 256;
            int kw = idx >> 6, n = idx & 63;
            int t0 = k0 + 2 * kw;
            float v0 = 0.f, v1 = 0.f;
            if (t0 < N_)     v0 = qkv[(size_t)(b * N_ + t0) * 2304 + 1536 + hh * 64 + n];
            if (t0 + 1 < N_) v1 = qkv[(size_t)(b * N_ + t0 + 1) * 2304 + 1536 + hh * 64 + n];
            Vs[kw * 72 + n] = packh2(v0, v1);
        }
        __syncthreads();
#pragma unroll
        for (int s = 0; s < 2; s++) {
            int abase = (wm * 16 + g) * 20 + s * 8 + tg;
            unsigned ah[4] = {As[abase], As[abase + 8 * 20], As[abase + 4], As[abase + 8 * 20 + 4]};
#pragma unroll
            for (int nf = 0; nf < 4; nf++) {
                int n = wn * 32 + nf * 8 + g;
                unsigned bf[2] = {Vs[(s * 8 + tg) * 72 + n], Vs[(s * 8 + tg + 4) * 72 + n]};
                mma_f16(acc[nf], ah, bf);
            }
        }
    }
#pragma unroll
    for (int nf = 0; nf < 4; nf++) {
        int col = wn * 32 + nf * 8 + 2 * tg;
#pragma unroll
        for (int hf = 0; hf < 2; hf++) {
            int m = m0 + wm * 16 + g + hf * 8;
            if (m < N_)
                aoh[(size_t)(b * N_ + m) * 384 + (hh * 64 + col) / 2] =
                    packh2(acc[nf][hf * 2 + 0], acc[nf][hf * 2 + 1]);
        }
    }
}

// ---------------- softmax ----------------
__global__ void softmax_kernel(float* __restrict__ attn)
{
    int row = blockIdx.x * 8 + (threadIdx.x >> 5);
    if (row >= BH_ * N_) return;
    int lane = threadIdx.x & 31;
    float* arow = attn + (size_t)row * N_;
    float v[7];
    float mx = -1e30f;
#pragma unroll
    for (int c = 0; c < 7; c++) {
        int j = lane + c * 32;
        v[c] = (j < N_) ? arow[j] : -1e30f;
        mx = fmaxf(mx, v[c]);
    }
    for (int off = 16; off; off >>= 1) mx = fmaxf(mx, __shfl_xor_sync(0xffffffffu, mx, off));
    float sum = 0.f;
#pragma unroll
    for (int c = 0; c < 7; c++) { float e = expf(v[c] - mx); v[c] = e; sum += e; }
    for (int off = 16; off; off >>= 1) sum += __shfl_xor_sync(0xffffffffu, sum, off);
    float inv = 1.f / sum;
#pragma unroll
    for (int c = 0; c < 7; c++) {
        int j = lane + c * 32;
        if (j < N_) arow[j] = v[c] * inv;
    }
}

// ---------------- selection ----------------
__global__ void select_kernel(const float* __restrict__ attn, int* __restrict__ ik,
                              int* __restrict__ ie)
{
    __shared__ float diag[196];
    __shared__ int kept[196];
    int b = blockIdx.x, tid = threadIdx.x;
    if (tid < 196) {
        float s = 0.f;
        for (int hh = 0; hh < H_; hh++)
            s += attn[((size_t)(b * H_ + hh) * N_ + (tid + 1)) * N_ + (tid + 1)];
        diag[tid] = s;
    }
    __syncthreads();
    if (tid < 196) {
        float di = diag[tid];
        int rank = 0;
        for (int j = 0; j < 196; j++) {
            float dj = diag[j];
            rank += (dj > di) || (dj == di && j < tid);
        }
        kept[tid] = (rank < NKEPT_) ? 1 : 0;
    }
    __syncthreads();
    if (tid < 196) {
        int mine = kept[tid];
        int pos = 0;
        for (int j = 0; j < tid; j++) pos += (kept[j] == mine);
        if (mine) ik[b * K_ + 1 + pos] = tid + 1;
        else      ie[b * R_ + pos]     = tid + 1;
    }
    if (tid == 0) ik[b * K_] = 0;
}

// ---------------- propagation ----------------
__global__ void propagate_kernel(const float* __restrict__ attn, const float* __restrict__ x1,
                                 const int* __restrict__ ikg, const int* __restrict__ ieg,
                                 float* __restrict__ x2)
{
    extern __shared__ float sm[];
    float* ws = sm;
    float* xe = sm + K_ * R_;
    __shared__ int ik[K_], ie[R_];
    __shared__ int cnt;
    int bh = blockIdx.x;
    int b = bh / H_, hh = bh % H_;
    int tid = threadIdx.x;
    if (tid < K_) ik[tid] = ikg[b * K_ + tid];
    if (tid < R_) ie[tid] = ieg[b * R_ + tid];
    __syncthreads();
    const float* ablk = attn + (size_t)bh * N_ * N_;
    for (int idx = tid; idx < K_ * R_; idx += 256) {
        int k = idx / R_, e = idx - k * R_;
        ws[idx] = ablk[(size_t)ik[k] * N_ + ie[e]];
    }
    for (int idx = tid; idx < R_ * 64; idx += 256) {
        int e = idx >> 6, d = idx & 63;
        xe[idx] = x1[(size_t)(b * N_ + ie[e]) * 768 + hh * 64 + d];
    }
    __syncthreads();

    unsigned lo = 0u, hi = 0x7f7fffffu;
    while (lo < hi) {
        unsigned mid = lo + ((hi - lo + 1) >> 1);
        if (tid == 0) cnt = 0;
        __syncthreads();
        int local = 0;
        for (int i = tid; i < K_ * R_; i += 256)
            local += (__float_as_uint(ws[i]) >= mid);
        for (int off = 16; off; off >>= 1) local += __shfl_xor_sync(0xffffffffu, local, off);
        if ((tid & 31) == 0) atomicAdd(&cnt, local);
        __syncthreads();
        int c = cnt;
        __syncthreads();
        if (c >= THRK_) lo = mid; else hi = mid - 1;
    }
    float thr = __uint_as_float(lo);

    for (int p = tid; p < K_ * 64; p += 256) {
        int k = p >> 6, d = p & 63;
        const float* wr = ws + k * R_;
        float acc = 0.f;
#pragma unroll 2
        for (int e = 0; e < R_; e++) {
            float wv = wr[e];
            wv = (wv >= thr) ? wv : 0.f;
            acc = fmaf(wv, xe[e * 64 + d], acc);
        }
        x2[(size_t)(b * K_ + k) * 768 + hh * 64 + d] =
            x1[(size_t)(b * N_ + ik[k]) * 768 + hh * 64 + d] + ALPHA_ * acc;
    }
}

// ---------------- host ----------------
extern "C" void kernel_launch(void* const* d_in, const int* in_sizes, int n_in,
                              void* d_out, int out_size)
{
    const float* x     = (const float*)d_in[0];
    const float* n1g   = (const float*)d_in[1];
    const float* n1b   = (const float*)d_in[2];
    const float* qkvw  = (const float*)d_in[3];
    const float* projw = (const float*)d_in[4];
    const float* projb = (const float*)d_in[5];
    const float* n2g   = (const float*)d_in[6];
    const float* n2b   = (const float*)d_in[7];
    const float* fc1w  = (const float*)d_in[8];
    const float* fc1b  = (const float*)d_in[9];
    const float* fc2w  = (const float*)d_in[10];
    const float* fc2b  = (const float*)d_in[11];
    float* out = (float*)d_out;

    float *qkv, *attn, *x1, *x2;
    int *ik, *ie;
    unsigned *hh, *hl, *aoh, *h2h, *mlph;
    __half *wqkvh, *wqkvl, *wprojh, *wfc1h, *wfc2h;
    cudaGetSymbolAddress((void**)&qkv,  g_qkv);
    cudaGetSymbolAddress((void**)&attn, g_attn);
    cudaGetSymbolAddress((void**)&x1,   g_x1);
    cudaGetSymbolAddress((void**)&x2,   g_x2);
    cudaGetSymbolAddress((void**)&ik,   g_ik);
    cudaGetSymbolAddress((void**)&ie,   g_ie);
    cudaGetSymbolAddress((void**)&hh,   g_hh);
    cudaGetSymbolAddress((void**)&hl,   g_hl);
    cudaGetSymbolAddress((void**)&wqkvh, g_wqkvh);
    cudaGetSymbolAddress((void**)&wqkvl, g_wqkvl);
    cudaGetSymbolAddress((void**)&wprojh, g_wprojh);
    cudaGetSymbolAddress((void**)&wfc1h, g_wfc1h);
    cudaGetSymbolAddress((void**)&wfc2h, g_wfc2h);
    cudaGetSymbolAddress((void**)&aoh,  g_aoh);
    cudaGetSymbolAddress((void**)&h2h,  g_h2h);
    cudaGetSymbolAddress((void**)&mlph, g_mlph);

    const int PROP_SMEM = (K_ * R_ + R_ * 64) * 4;
    cudaFuncSetAttribute(propagate_kernel, cudaFuncAttributeMaxDynamicSharedMemorySize, PROP_SMEM);
    const int SMEM_PLAIN = (ABUF + BBUF) * 2 * 2;       // 27648 B
    const int SMEM_SPLIT = (ABUF + BBUF) * 4 * 2;       // 55296 B
    cudaFuncSetAttribute(hgemm_kernel<1, false, false, false, false>,
                         cudaFuncAttributeMaxDynamicSharedMemorySize, SMEM_SPLIT);
    cudaFuncSetAttribute(hgemm_kernel<0, false, false, false, false>,
                         cudaFuncAttributeMaxDynamicSharedMemorySize, SMEM_PLAIN);
    cudaFuncSetAttribute(hgemm_kernel<0, false, true, true, false>,
                         cudaFuncAttributeMaxDynamicSharedMemorySize, SMEM_PLAIN);
    cudaFuncSetAttribute(hgemm_kernel<0, true, true, false, true>,
                         cudaFuncAttributeMaxDynamicSharedMemorySize, SMEM_PLAIN);

    // 0. weight conversion (plain half [K][N]; lo for QKV)
    cvtw_h<1><<<(768 * 2304) / 2048, 256>>>(qkvw, wqkvh, wqkvl, 768 * 2304);
    cvtw_h<0><<<(768 * 768) / 2048, 256>>>(projw, wprojh, nullptr, 768 * 768);
    cvtw_h<0><<<(768 * 3072) / 2048, 256>>>(fc1w, wfc1h, nullptr, 768 * 3072);
    cvtw_h<0><<<(3072 * 768) / 2048, 256>>>(fc2w, wfc2h, nullptr, 3072 * 768);

    // 1. LN1 -> packed fp16 hi/lo
    ln_pack_kernel<1><<<B_ * N_, 256>>>(x, n1g, n1b, hh, hl);
    // 2a. QK columns [0,1536) split-fp16 (rank-safe)
    hgemm_kernel<1, false, false, false, false><<<dim3(12, 197), 256, SMEM_SPLIT>>>(
        hh, hl, wqkvh, wqkvl, nullptr, nullptr, qkv, nullptr, 2304, C_, 2304, 0);
    // 2b. V columns [1536,2304) plain fp16
    hgemm_kernel<0, false, false, false, false><<<dim3(6, 197), 256, SMEM_PLAIN>>>(
        hh, nullptr, wqkvh, nullptr, nullptr, nullptr, qkv, nullptr, 2304, C_, 2304, 1536);
    // 3. scores (split-fp16 MMA)
    score_mma<<<dim3(BH_, 4, 4), 256>>>(qkv, attn);
    // 4. softmax
    softmax_kernel<<<(BH_ * N_ + 7) / 8, 256>>>(attn);
    // 5. attn @ V (fp16 MMA) -> packed fp16 ao
    av_mma<<<dim3(BH_, 4), 256>>>(attn, qkv, aoh);
    // 6. proj + bias + residual
    hgemm_kernel<0, false, true, true, false><<<dim3(6, 197), 256, SMEM_PLAIN>>>(
        aoh, nullptr, wprojh, nullptr, projb, x, x1, nullptr, C_, C_, C_, 0);
    // 7. selection
    select_kernel<<<B_, 256>>>(attn, ik, ie);
    // 8. propagation
    propagate_kernel<<<BH_, 256, PROP_SMEM>>>(attn, x1, ik, ie, x2);
    // 9. LN2 -> packed fp16
    ln_pack_kernel<0><<<B_ * K_, 256>>>(x2, n2g, n2b, h2h, nullptr);
    // 10. fc1 + gelu -> packed fp16
    hgemm_kernel<0, true, true, false, true><<<dim3(24, 99), 256, SMEM_PLAIN>>>(
        h2h, nullptr, wfc1h, nullptr, fc1b, nullptr, nullptr, mlph, 4 * C_, C_, 0, 0);
    // 11. fc2 + residual -> out
    hgemm_kernel<0, false, true, true, false><<<dim3(6, 99), 256, SMEM_PLAIN>>>(
        mlph, nullptr, wfc2h, nullptr, fc2b, x2, out, nullptr, C_, 4 * C_, C_, 0);
}

// round 9
// speedup vs baseline: 1.4173x; 1.1378x over previous
#include <cuda_runtime.h>
#include <cuda_fp16.h>
#include <math.h>

#define B_   64
#define N_   197
#define C_   768
#define H_   12
#define R_   98
#define K_   99
#define NKEPT_ 98
#define THRK_ 1941
#define ALPHA_ 0.1f
#define EPS_ 1e-5f
#define BH_  (B_*H_)

// ---------------- scratch ----------------
__device__ float    g_qkv [(size_t)B_*N_*3*C_];
__device__ float    g_attn[(size_t)BH_*N_*N_];
__device__ float    g_x1  [(size_t)B_*N_*C_];
__device__ float    g_x2  [(size_t)B_*K_*C_];
__device__ int      g_ik  [B_*K_];
__device__ int      g_ie  [B_*R_];
__device__ unsigned g_hh  [(size_t)B_*N_*C_/2];
__device__ unsigned g_hl  [(size_t)B_*N_*C_/2];
__device__ __half   g_wqkvh[(size_t)C_*3*C_];
__device__ __half   g_wqkvl[(size_t)C_*3*C_];
__device__ __half   g_wprojh[(size_t)C_*C_];
__device__ __half   g_wfc1h[(size_t)C_*4*C_];
__device__ __half   g_wfc2h[(size_t)4*C_*C_];
__device__ unsigned g_aoh [(size_t)B_*N_*C_/2];
__device__ unsigned g_h2h [(size_t)B_*K_*C_/2];
__device__ unsigned g_mlph[(size_t)B_*K_*4*C_/2];

// ---------------- helpers ----------------
__device__ __forceinline__ unsigned packh2(float a, float b) {
    __half2 h = __floats2half2_rn(a, b);
    return *reinterpret_cast<unsigned*>(&h);
}
__device__ __forceinline__ void splith2(float a, float b, unsigned& hi, unsigned& lo) {
    __half ah = __float2half_rn(a), bh = __float2half_rn(b);
    __half2 h = __halves2half2(ah, bh);
    hi = *reinterpret_cast<unsigned*>(&h);
    lo = packh2(a - __half2float(ah), b - __half2float(bh));
}
__device__ __forceinline__ unsigned sm_u32(const void* p) {
    return (unsigned)__cvta_generic_to_shared(p);
}
__device__ __forceinline__ void ldsm4(unsigned r[4], unsigned a) {
    asm volatile("ldmatrix.sync.aligned.m8n8.x4.shared.b16 {%0,%1,%2,%3}, [%4];"
                 : "=r"(r[0]), "=r"(r[1]), "=r"(r[2]), "=r"(r[3]) : "r"(a));
}
__device__ __forceinline__ void ldsm4t(unsigned r[4], unsigned a) {
    asm volatile("ldmatrix.sync.aligned.m8n8.x4.trans.shared.b16 {%0,%1,%2,%3}, [%4];"
                 : "=r"(r[0]), "=r"(r[1]), "=r"(r[2]), "=r"(r[3]) : "r"(a));
}
__device__ __forceinline__ void mma_f16(float c[4], const unsigned a[4], const unsigned b[2]) {
    asm volatile(
        "mma.sync.aligned.m16n8k16.row.col.f32.f16.f16.f32 "
        "{%0,%1,%2,%3},{%4,%5,%6,%7},{%8,%9},{%0,%1,%2,%3};"
        : "+f"(c[0]), "+f"(c[1]), "+f"(c[2]), "+f"(c[3])
        : "r"(a[0]), "r"(a[1]), "r"(a[2]), "r"(a[3]), "r"(b[0]), "r"(b[1]));
}

// ---------------- weight convert: fp32 [K][N] -> half [K][N] (hi, opt lo) ----------
template<int SPLIT>
__global__ void cvtw_h(const float* __restrict__ w, __half* __restrict__ hi,
                       __half* __restrict__ lo, int n)
{
    int i = (blockIdx.x * 256 + threadIdx.x) * 8;
    if (i >= n) return;
    float4 a = *(const float4*)&w[i];
    float4 b = *(const float4*)&w[i + 4];
    __half2 h[4];
    h[0] = __floats2half2_rn(a.x, a.y); h[1] = __floats2half2_rn(a.z, a.w);
    h[2] = __floats2half2_rn(b.x, b.y); h[3] = __floats2half2_rn(b.z, b.w);
    *(uint4*)&hi[i] = *(uint4*)h;
    if (SPLIT) {
        __half2 l[4];
        l[0] = __floats2half2_rn(a.x - __low2float(h[0]), a.y - __high2float(h[0]));
        l[1] = __floats2half2_rn(a.z - __low2float(h[1]), a.w - __high2float(h[1]));
        l[2] = __floats2half2_rn(b.x - __low2float(h[2]), b.y - __high2float(h[2]));
        l[3] = __floats2half2_rn(b.z - __low2float(h[3]), b.w - __high2float(h[3]));
        *(uint4*)&lo[i] = *(uint4*)l;
    }
}

// ---------------- LayerNorm -> packed fp16 hi(/lo) ----------------
template<int SPLIT>
__global__ void ln_pack_kernel(const float* __restrict__ x, const float* __restrict__ g,
                               const float* __restrict__ bta,
                               unsigned* __restrict__ hi, unsigned* __restrict__ lo)
{
    int row = blockIdx.x;
    const float2* xr = (const float2*)(x + (size_t)row * C_);
    int tid = threadIdx.x;
    float2 v1 = xr[tid];
    float2 v2 = make_float2(0.f, 0.f);
    if (tid < 128) v2 = xr[tid + 256];
    float s = v1.x + v1.y + v2.x + v2.y;
    float ss = v1.x * v1.x + v1.y * v1.y + v2.x * v2.x + v2.y * v2.y;
    for (int off = 16; off; off >>= 1) {
        s  += __shfl_xor_sync(0xffffffffu, s, off);
        ss += __shfl_xor_sync(0xffffffffu, ss, off);
    }
    __shared__ float rs[8], rss[8];
    __shared__ float smean, srstd;
    int w = tid >> 5;
    if ((tid & 31) == 0) { rs[w] = s; rss[w] = ss; }
    __syncthreads();
    if (tid == 0) {
        float S = 0.f, SS = 0.f;
        for (int i = 0; i < 8; i++) { S += rs[i]; SS += rss[i]; }
        float mean = S * (1.f / C_);
        float var = SS * (1.f / C_) - mean * mean;
        smean = mean; srstd = rsqrtf(var + EPS_);
    }
    __syncthreads();
    float mean = smean, rstd = srstd;
    size_t base = (size_t)row * (C_ / 2);
#pragma unroll
    for (int p = 0; p < 2; p++) {
        if (p == 1 && tid >= 128) break;
        int wi = tid + p * 256;
        float2 v = (p == 0) ? v1 : v2;
        int c = wi * 2;
        float a = (v.x - mean) * rstd * g[c] + bta[c];
        float b = (v.y - mean) * rstd * g[c + 1] + bta[c + 1];
        if (SPLIT) { unsigned h, l; splith2(a, b, h, l); hi[base + wi] = h; lo[base + wi] = l; }
        else hi[base + wi] = packh2(a, b);
    }
}

// ---------------- fp16 GEMM: 64x256 tile, k32 steps, ldmatrix, double-buffered ----
#define AST 40
#define BST 264
#define ABUF (64 * AST)
#define BBUF (32 * BST)

template<int SPLIT>
__device__ __forceinline__ void hg_compute(const __half* buf, const int aoff[2],
                                           const int boff[4], float acc[2][8][4])
{
    const __half* AsH = buf;
    const __half* AsL = buf + ABUF;
    const __half* BsH = buf + ABUF * (1 + SPLIT);
    const __half* BsL = BsH + BBUF;
#pragma unroll
    for (int s = 0; s < 2; s++) {
        unsigned ah[2][4], al[2][4];
#pragma unroll
        for (int mf = 0; mf < 2; mf++) {
            ldsm4(ah[mf], sm_u32(AsH + aoff[mf] + s * 16));
            if (SPLIT) ldsm4(al[mf], sm_u32(AsL + aoff[mf] + s * 16));
        }
        unsigned bhf[8][2], blf[8][2];
#pragma unroll
        for (int p = 0; p < 4; p++) {
            unsigned r[4];
            ldsm4t(r, sm_u32(BsH + boff[p] + s * 16 * BST));
            bhf[2*p][0] = r[0]; bhf[2*p][1] = r[1];
            bhf[2*p+1][0] = r[2]; bhf[2*p+1][1] = r[3];
            if (SPLIT) {
                unsigned rl[4];
                ldsm4t(rl, sm_u32(BsL + boff[p] + s * 16 * BST));
                blf[2*p][0] = rl[0]; blf[2*p][1] = rl[1];
                blf[2*p+1][0] = rl[2]; blf[2*p+1][1] = rl[3];
            }
        }
#pragma unroll
        for (int mf = 0; mf < 2; mf++)
#pragma unroll
            for (int nf = 0; nf < 8; nf++) {
                mma_f16(acc[mf][nf], ah[mf], bhf[nf]);
                if (SPLIT) {
                    mma_f16(acc[mf][nf], ah[mf], blf[nf]);
                    mma_f16(acc[mf][nf], al[mf], bhf[nf]);
                }
            }
    }
}

template<int SPLIT, bool GELU, bool HASBIAS, bool HASRES, bool OUTPACK>
__global__ void __launch_bounds__(256, 2)
hgemm_kernel(const unsigned* __restrict__ Ah, const unsigned* __restrict__ Al,
             const __half* __restrict__ Bh, const __half* __restrict__ Bl,
             const float* __restrict__ bias, const float* __restrict__ res,
             float* __restrict__ Cf, unsigned* __restrict__ Cu,
             int Nd, int Kd, int ldc, int n0ofs)
{
    extern __shared__ __half sh[];
    const int UNIT = (ABUF + BBUF) * (1 + SPLIT);
    int tid = threadIdx.x, lane = tid & 31, wid = tid >> 5;
    int wm = wid & 1, wn = wid >> 1;
    int g = lane >> 2, tg = lane & 3;
    int m0 = blockIdx.y * 64, n0 = blockIdx.x * 256 + n0ofs;
    int Kw = Kd / 2;

    float acc[2][8][4];
#pragma unroll
    for (int i = 0; i < 2; i++)
#pragma unroll
        for (int j = 0; j < 8; j++)
#pragma unroll
            for (int q = 0; q < 4; q++) acc[i][j][q] = 0.f;

    int ar = tid >> 2, agw = (tid & 3) * 4;          // A: word row/col
    int bkr = tid >> 5, bn8 = (tid & 31) * 8;        // B: half row (0..7) / col
    const unsigned* ApH = Ah + (size_t)(m0 + ar) * Kw + agw;
    const unsigned* ApL = SPLIT ? Al + (size_t)(m0 + ar) * Kw + agw : ApH;
    const __half* BpH = Bh + (size_t)bkr * Nd + n0 + bn8;
    const __half* BpL = SPLIT ? Bl + (size_t)bkr * Nd + n0 + bn8 : BpH;

    int aSts = ar * AST + (tid & 3) * 8;
    int bSts = bkr * BST + bn8;

    int aoff[2], boff[4];
#pragma unroll
    for (int mf = 0; mf < 2; mf++)
        aoff[mf] = (wm * 32 + mf * 16 + (lane & 15)) * AST + (lane >> 4) * 8;
#pragma unroll
    for (int p = 0; p < 4; p++)
        boff[p] = (lane & 15) * BST + wn * 64 + p * 16 + (lane >> 4) * 8;

    uint4 rah, ral, rbh[4], rbl[4];
    rah = *(const uint4*)ApH;
    if (SPLIT) ral = *(const uint4*)ApL;
#pragma unroll
    for (int j = 0; j < 4; j++) {
        rbh[j] = *(const uint4*)(BpH + (size_t)j * 8 * Nd);
        if (SPLIT) rbl[j] = *(const uint4*)(BpL + (size_t)j * 8 * Nd);
    }
    {
        __half* buf = sh;
        *(uint4*)&buf[aSts] = rah;
        if (SPLIT) *(uint4*)&buf[ABUF + aSts] = ral;
        __half* bb = buf + ABUF * (1 + SPLIT);
#pragma unroll
        for (int j = 0; j < 4; j++) {
            *(uint4*)&bb[bSts + j * 8 * BST] = rbh[j];
            if (SPLIT) *(uint4*)&bb[BBUF + bSts + j * 8 * BST] = rbl[j];
        }
    }
    __syncthreads();

    int nit = Kd / 32;
    for (int it = 1; it < nit; it++) {
        rah = *(const uint4*)(ApH + it * 16);
        if (SPLIT) ral = *(const uint4*)(ApL + it * 16);
#pragma unroll
        for (int j = 0; j < 4; j++) {
            rbh[j] = *(const uint4*)(BpH + (size_t)(it * 32 + j * 8) * Nd);
            if (SPLIT) rbl[j] = *(const uint4*)(BpL + (size_t)(it * 32 + j * 8) * Nd);
        }
        hg_compute<SPLIT>(sh + ((it - 1) & 1) * UNIT, aoff, boff, acc);
        {
            __half* buf = sh + (it & 1) * UNIT;
            *(uint4*)&buf[aSts] = rah;
            if (SPLIT) *(uint4*)&buf[ABUF + aSts] = ral;
            __half* bb = buf + ABUF * (1 + SPLIT);
#pragma unroll
            for (int j = 0; j < 4; j++) {
                *(uint4*)&bb[bSts + j * 8 * BST] = rbh[j];
                if (SPLIT) *(uint4*)&bb[BBUF + bSts + j * 8 * BST] = rbl[j];
            }
        }
        __syncthreads();
    }
    hg_compute<SPLIT>(sh + ((nit - 1) & 1) * UNIT, aoff, boff, acc);

    // epilogue
#pragma unroll
    for (int mf = 0; mf < 2; mf++) {
        int row = m0 + wm * 32 + mf * 16 + g;
#pragma unroll
        for (int nf = 0; nf < 8; nf++) {
            int col = n0 + wn * 64 + nf * 8 + 2 * tg;
            float b0 = 0.f, b1 = 0.f;
            if (HASBIAS) { b0 = bias[col]; b1 = bias[col + 1]; }
#pragma unroll
            for (int half = 0; half < 2; half++) {
                int r = row + half * 8;
                float c0 = acc[mf][nf][half * 2 + 0] + b0;
                float c1 = acc[mf][nf][half * 2 + 1] + b1;
                if (GELU) {
                    c0 = 0.5f * c0 * (1.f + erff(c0 * 0.70710678118654752f));
                    c1 = 0.5f * c1 * (1.f + erff(c1 * 0.70710678118654752f));
                }
                if (OUTPACK) {
                    Cu[(size_t)r * (Nd / 2) + col / 2] = packh2(c0, c1);
                } else {
                    size_t base = (size_t)r * ldc + col;
                    if (HASRES) {
                        float2 rv = *(const float2*)&res[base];
                        c0 += rv.x; c1 += rv.y;
                    }
                    float2 ov; ov.x = c0; ov.y = c1;
                    *(float2*)&Cf[base] = ov;
                }
            }
        }
    }
}

// ---------------- scores: split-fp16 MMA, 64x64 per block ----------------
__global__ void score_mma(const float* __restrict__ qkv, float* __restrict__ attn)
{
    __shared__ unsigned Qh[64 * 36], Ql[64 * 36], Kh[32 * 72], Kl[32 * 72];
    int bh = blockIdx.x, b = bh / H_, hh = bh % H_;
    int m0 = blockIdx.y * 64, n0 = blockIdx.z * 64;
    int tid = threadIdx.x, lane = tid & 31, wid = tid >> 5;
    int g = lane >> 2, tg = lane & 3;
    int wm = wid & 3, wn = wid >> 2;

#pragma unroll
    for (int r = 0; r < 8; r++) {
        int idx = tid + r * 256;
        int row = idx >> 5, kw = idx & 31;
        int mq = m0 + row, nk = n0 + row;
        float2 qv = make_float2(0.f, 0.f), kv = make_float2(0.f, 0.f);
        if (mq < N_) qv = *(const float2*)&qkv[(size_t)(b * N_ + mq) * 2304 + hh * 64 + 2 * kw];
        if (nk < N_) kv = *(const float2*)&qkv[(size_t)(b * N_ + nk) * 2304 + 768 + hh * 64 + 2 * kw];
        unsigned h, l;
        splith2(qv.x * 0.125f, qv.y * 0.125f, h, l);
        Qh[row * 36 + kw] = h; Ql[row * 36 + kw] = l;
        splith2(kv.x, kv.y, h, l);
        Kh[kw * 72 + row] = h; Kl[kw * 72 + row] = l;
    }
    __syncthreads();

    float acc[4][4];
#pragma unroll
    for (int i = 0; i < 4; i++)
#pragma unroll
        for (int j = 0; j < 4; j++) acc[i][j] = 0.f;

#pragma unroll
    for (int s = 0; s < 4; s++) {
        int abase = (wm * 16 + g) * 36 + s * 8 + tg;
        unsigned ah[4] = {Qh[abase], Qh[abase + 8 * 36], Qh[abase + 4], Qh[abase + 8 * 36 + 4]};
        unsigned al[4] = {Ql[abase], Ql[abase + 8 * 36], Ql[abase + 4], Ql[abase + 8 * 36 + 4]};
#pragma unroll
        for (int nf = 0; nf < 4; nf++) {
            int n = wn * 32 + nf * 8 + g;
            unsigned bhf[2] = {Kh[(s * 8 + tg) * 72 + n], Kh[(s * 8 + tg + 4) * 72 + n]};
            unsigned blf[2] = {Kl[(s * 8 + tg) * 72 + n], Kl[(s * 8 + tg + 4) * 72 + n]};
            mma_f16(acc[nf], ah, bhf);
            mma_f16(acc[nf], ah, blf);
            mma_f16(acc[nf], al, bhf);
        }
    }
#pragma unroll
    for (int nf = 0; nf < 4; nf++) {
        int col = n0 + wn * 32 + nf * 8 + 2 * tg;
#pragma unroll
        for (int hf = 0; hf < 2; hf++) {
            int row = m0 + wm * 16 + g + hf * 8;
            if (row < N_) {
                float* arow = attn + ((size_t)bh * N_ + row) * N_;
                if (col < N_)     arow[col]     = acc[nf][hf * 2 + 0];
                if (col + 1 < N_) arow[col + 1] = acc[nf][hf * 2 + 1];
            }
        }
    }
}

// ---------------- AV: plain-fp16 MMA, 64x64 per block ----------------
__global__ void av_mma(const float* __restrict__ attn, const float* __restrict__ qkv,
                       unsigned* __restrict__ aoh)
{
    __shared__ unsigned As[64 * 20], Vs[32 * 72];
    int bh = blockIdx.x, b = bh / H_, hh = bh % H_;
    int m0 = blockIdx.y * 64;
    int tid = threadIdx.x, lane = tid & 31, wid = tid >> 5;
    int g = lane >> 2, tg = lane & 3;
    int wm = wid & 3, wn = wid >> 2;

    float acc[4][4];
#pragma unroll
    for (int i = 0; i < 4; i++)
#pragma unroll
        for (int j = 0; j < 4; j++) acc[i][j] = 0.f;

    for (int k0 = 0; k0 < 224; k0 += 32) {
        __syncthreads();
#pragma unroll
        for (int r = 0; r < 4; r++) {
            int idx = tid + r * 256;
            int m = idx >> 4, kw = idx & 15;
            int mg = m0 + m, t0 = k0 + 2 * kw;
            float a0 = 0.f, a1 = 0.f;
            if (mg < N_) {
                const float* arow = attn + ((size_t)bh * N_ + mg) * N_;
                if (t0 < N_)     a0 = arow[t0];
                if (t0 + 1 < N_) a1 = arow[t0 + 1];
            }
            As[m * 20 + kw] = packh2(a0, a1);
        }
#pragma unroll
        for (int r = 0; r < 4; r++) {
            int idx = tid + r * 256;
            int kw = idx >> 6, n = idx & 63;
            int t0 = k0 + 2 * kw;
            float v0 = 0.f, v1 = 0.f;
            if (t0 < N_)     v0 = qkv[(size_t)(b * N_ + t0) * 2304 + 1536 + hh * 64 + n];
            if (t0 + 1 < N_) v1 = qkv[(size_t)(b * N_ + t0 + 1) * 2304 + 1536 + hh * 64 + n];
            Vs[kw * 72 + n] = packh2(v0, v1);
        }
        __syncthreads();
#pragma unroll
        for (int s = 0; s < 2; s++) {
            int abase = (wm * 16 + g) * 20 + s * 8 + tg;
            unsigned ah[4] = {As[abase], As[abase + 8 * 20], As[abase + 4], As[abase + 8 * 20 + 4]};
#pragma unroll
            for (int nf = 0; nf < 4; nf++) {
                int n = wn * 32 + nf * 8 + g;
                unsigned bf[2] = {Vs[(s * 8 + tg) * 72 + n], Vs[(s * 8 + tg + 4) * 72 + n]};
                mma_f16(acc[nf], ah, bf);
            }
        }
    }
#pragma unroll
    for (int nf = 0; nf < 4; nf++) {
        int col = wn * 32 + nf * 8 + 2 * tg;
#pragma unroll
        for (int hf = 0; hf < 2; hf++) {
            int m = m0 + wm * 16 + g + hf * 8;
            if (m < N_)
                aoh[(size_t)(b * N_ + m) * 384 + (hh * 64 + col) / 2] =
                    packh2(acc[nf][hf * 2 + 0], acc[nf][hf * 2 + 1]);
        }
    }
}

// ---------------- softmax ----------------
__global__ void softmax_kernel(float* __restrict__ attn)
{
    int row = blockIdx.x * 8 + (threadIdx.x >> 5);
    if (row >= BH_ * N_) return;
    int lane = threadIdx.x & 31;
    float* arow = attn + (size_t)row * N_;
    float v[7];
    float mx = -1e30f;
#pragma unroll
    for (int c = 0; c < 7; c++) {
        int j = lane + c * 32;
        v[c] = (j < N_) ? arow[j] : -1e30f;
        mx = fmaxf(mx, v[c]);
    }
    for (int off = 16; off; off >>= 1) mx = fmaxf(mx, __shfl_xor_sync(0xffffffffu, mx, off));
    float sum = 0.f;
#pragma unroll
    for (int c = 0; c < 7; c++) { float e = expf(v[c] - mx); v[c] = e; sum += e; }
    for (int off = 16; off; off >>= 1) sum += __shfl_xor_sync(0xffffffffu, sum, off);
    float inv = 1.f / sum;
#pragma unroll
    for (int c = 0; c < 7; c++) {
        int j = lane + c * 32;
        if (j < N_) arow[j] = v[c] * inv;
    }
}

// ---------------- selection ----------------
__global__ void select_kernel(const float* __restrict__ attn, int* __restrict__ ik,
                              int* __restrict__ ie)
{
    __shared__ float diag[196];
    __shared__ int kept[196];
    int b = blockIdx.x, tid = threadIdx.x;
    if (tid < 196) {
        float s = 0.f;
        for (int hh = 0; hh < H_; hh++)
            s += attn[((size_t)(b * H_ + hh) * N_ + (tid + 1)) * N_ + (tid + 1)];
        diag[tid] = s;
    }
    __syncthreads();
    if (tid < 196) {
        float di = diag[tid];
        int rank = 0;
        for (int j = 0; j < 196; j++) {
            float dj = diag[j];
            rank += (dj > di) || (dj == di && j < tid);
        }
        kept[tid] = (rank < NKEPT_) ? 1 : 0;
    }
    __syncthreads();
    if (tid < 196) {
        int mine = kept[tid];
        int pos = 0;
        for (int j = 0; j < tid; j++) pos += (kept[j] == mine);
        if (mine) ik[b * K_ + 1 + pos] = tid + 1;
        else      ie[b * R_ + pos]     = tid + 1;
    }
    if (tid == 0) ik[b * K_] = 0;
}

// ---------------- propagation ----------------
__global__ void propagate_kernel(const float* __restrict__ attn, const float* __restrict__ x1,
                                 const int* __restrict__ ikg, const int* __restrict__ ieg,
                                 float* __restrict__ x2)
{
    extern __shared__ float sm[];
    float* ws = sm;
    float* xe = sm + K_ * R_;
    __shared__ int ik[K_], ie[R_];
    __shared__ int cnt;
    int bh = blockIdx.x;
    int b = bh / H_, hh = bh % H_;
    int tid = threadIdx.x;
    if (tid < K_) ik[tid] = ikg[b * K_ + tid];
    if (tid < R_) ie[tid] = ieg[b * R_ + tid];
    __syncthreads();
    const float* ablk = attn + (size_t)bh * N_ * N_;
    for (int idx = tid; idx < K_ * R_; idx += 256) {
        int k = idx / R_, e = idx - k * R_;
        ws[idx] = ablk[(size_t)ik[k] * N_ + ie[e]];
    }
    for (int idx = tid; idx < R_ * 64; idx += 256) {
        int e = idx >> 6, d = idx & 63;
        xe[idx] = x1[(size_t)(b * N_ + ie[e]) * 768 + hh * 64 + d];
    }
    __syncthreads();

    unsigned lo = 0u, hi = 0x7f7fffffu;
    while (lo < hi) {
        unsigned mid = lo + ((hi - lo + 1) >> 1);
        if (tid == 0) cnt = 0;
        __syncthreads();
        int local = 0;
        for (int i = tid; i < K_ * R_; i += 256)
            local += (__float_as_uint(ws[i]) >= mid);
        for (int off = 16; off; off >>= 1) local += __shfl_xor_sync(0xffffffffu, local, off);
        if ((tid & 31) == 0) atomicAdd(&cnt, local);
        __syncthreads();
        int c = cnt;
        __syncthreads();
        if (c >= THRK_) lo = mid; else hi = mid - 1;
    }
    float thr = __uint_as_float(lo);

    for (int p = tid; p < K_ * 64; p += 256) {
        int k = p >> 6, d = p & 63;
        const float* wr = ws + k * R_;
        float acc = 0.f;
#pragma unroll 2
        for (int e = 0; e < R_; e++) {
            float wv = wr[e];
            wv = (wv >= thr) ? wv : 0.f;
            acc = fmaf(wv, xe[e * 64 + d], acc);
        }
        x2[(size_t)(b * K_ + k) * 768 + hh * 64 + d] =
            x1[(size_t)(b * N_ + ik[k]) * 768 + hh * 64 + d] + ALPHA_ * acc;
    }
}

// ---------------- host ----------------
extern "C" void kernel_launch(void* const* d_in, const int* in_sizes, int n_in,
                              void* d_out, int out_size)
{
    const float* x     = (const float*)d_in[0];
    const float* n1g   = (const float*)d_in[1];
    const float* n1b   = (const float*)d_in[2];
    const float* qkvw  = (const float*)d_in[3];
    const float* projw = (const float*)d_in[4];
    const float* projb = (const float*)d_in[5];
    const float* n2g   = (const float*)d_in[6];
    const float* n2b   = (const float*)d_in[7];
    const float* fc1w  = (const float*)d_in[8];
    const float* fc1b  = (const float*)d_in[9];
    const float* fc2w  = (const float*)d_in[10];
    const float* fc2b  = (const float*)d_in[11];
    float* out = (float*)d_out;

    float *qkv, *attn, *x1, *x2;
    int *ik, *ie;
    unsigned *hh, *hl, *aoh, *h2h, *mlph;
    __half *wqkvh, *wqkvl, *wprojh, *wfc1h, *wfc2h;
    cudaGetSymbolAddress((void**)&qkv,  g_qkv);
    cudaGetSymbolAddress((void**)&attn, g_attn);
    cudaGetSymbolAddress((void**)&x1,   g_x1);
    cudaGetSymbolAddress((void**)&x2,   g_x2);
    cudaGetSymbolAddress((void**)&ik,   g_ik);
    cudaGetSymbolAddress((void**)&ie,   g_ie);
    cudaGetSymbolAddress((void**)&hh,   g_hh);
    cudaGetSymbolAddress((void**)&hl,   g_hl);
    cudaGetSymbolAddress((void**)&wqkvh, g_wqkvh);
    cudaGetSymbolAddress((void**)&wqkvl, g_wqkvl);
    cudaGetSymbolAddress((void**)&wprojh, g_wprojh);
    cudaGetSymbolAddress((void**)&wfc1h, g_wfc1h);
    cudaGetSymbolAddress((void**)&wfc2h, g_wfc2h);
    cudaGetSymbolAddress((void**)&aoh,  g_aoh);
    cudaGetSymbolAddress((void**)&h2h,  g_h2h);
    cudaGetSymbolAddress((void**)&mlph, g_mlph);

    const int PROP_SMEM = (K_ * R_ + R_ * 64) * 4;
    cudaFuncSetAttribute(propagate_kernel, cudaFuncAttributeMaxDynamicSharedMemorySize, PROP_SMEM);
    const int SMEM_PLAIN = (ABUF + BBUF) * 2 * 2;       // 44032 B
    const int SMEM_SPLIT = (ABUF + BBUF) * 4 * 2;       // 88064 B
    cudaFuncSetAttribute(hgemm_kernel<1, false, false, false, false>,
                         cudaFuncAttributeMaxDynamicSharedMemorySize, SMEM_SPLIT);
    cudaFuncSetAttribute(hgemm_kernel<0, false, false, false, false>,
                         cudaFuncAttributeMaxDynamicSharedMemorySize, SMEM_PLAIN);
    cudaFuncSetAttribute(hgemm_kernel<0, false, true, true, false>,
                         cudaFuncAttributeMaxDynamicSharedMemorySize, SMEM_PLAIN);
    cudaFuncSetAttribute(hgemm_kernel<0, true, true, false, true>,
                         cudaFuncAttributeMaxDynamicSharedMemorySize, SMEM_PLAIN);

    // 0. weight conversion
    cvtw_h<1><<<(768 * 2304) / 2048, 256>>>(qkvw, wqkvh, wqkvl, 768 * 2304);
    cvtw_h<0><<<(768 * 768) / 2048, 256>>>(projw, wprojh, nullptr, 768 * 768);
    cvtw_h<0><<<(768 * 3072) / 2048, 256>>>(fc1w, wfc1h, nullptr, 768 * 3072);
    cvtw_h<0><<<(3072 * 768) / 2048, 256>>>(fc2w, wfc2h, nullptr, 3072 * 768);

    // 1. LN1 -> packed fp16 hi/lo
    ln_pack_kernel<1><<<B_ * N_, 256>>>(x, n1g, n1b, hh, hl);
    // 2a. QK columns [0,1536) split-fp16 (rank-safe)
    hgemm_kernel<1, false, false, false, false><<<dim3(6, 197), 256, SMEM_SPLIT>>>(
        hh, hl, wqkvh, wqkvl, nullptr, nullptr, qkv, nullptr, 2304, C_, 2304, 0);
    // 2b. V columns [1536,2304) plain fp16
    hgemm_kernel<0, false, false, false, false><<<dim3(3, 197), 256, SMEM_PLAIN>>>(
        hh, nullptr, wqkvh, nullptr, nullptr, nullptr, qkv, nullptr, 2304, C_, 2304, 1536);
    // 3. scores (split-fp16 MMA)
    score_mma<<<dim3(BH_, 4, 4), 256>>>(qkv, attn);
    // 4. softmax
    softmax_kernel<<<(BH_ * N_ + 7) / 8, 256>>>(attn);
    // 5. attn @ V (fp16 MMA) -> packed fp16 ao
    av_mma<<<dim3(BH_, 4), 256>>>(attn, qkv, aoh);
    // 6. proj + bias + residual
    hgemm_kernel<0, false, true, true, false><<<dim3(3, 197), 256, SMEM_PLAIN>>>(
        aoh, nullptr, wprojh, nullptr, projb, x, x1, nullptr, C_, C_, C_, 0);
    // 7. selection
    select_kernel<<<B_, 256>>>(attn, ik, ie);
    // 8. propagation
    propagate_kernel<<<BH_, 256, PROP_SMEM>>>(attn, x1, ik, ie, x2);
    // 9. LN2 -> packed fp16
    ln_pack_kernel<0><<<B_ * K_, 256>>>(x2, n2g, n2b, h2h, nullptr);
    // 10. fc1 + gelu -> packed fp16
    hgemm_kernel<0, true, true, false, true><<<dim3(12, 99), 256, SMEM_PLAIN>>>(
        h2h, nullptr, wfc1h, nullptr, fc1b, nullptr, nullptr, mlph, 4 * C_, C_, 0, 0);
    // 11. fc2 + residual -> out
    hgemm_kernel<0, false, true, true, false><<<dim3(3, 99), 256, SMEM_PLAIN>>>(
        mlph, nullptr, wfc2h, nullptr, fc2b, x2, out, nullptr, C_, 4 * C_, C_, 0);
}